// round 6
// baseline (speedup 1.0000x reference)
#include <cuda_runtime.h>
#include <cstdint>
#include <math.h>

#define BATCH 4
#define LEN 2048
#define DMODEL 1024
#define NH 8
#define DHEAD 128
#define MROWS (BATCH * LEN)

__device__ float g_Q[NH * BATCH * LEN * DHEAD];    // [h][b][l][d]
__device__ float g_K[NH * BATCH * LEN * DHEAD];
__device__ float g_V[NH * BATCH * LEN * DHEAD];
__device__ float g_ctx[BATCH * LEN * DMODEL];      // [b][l][h*128+d]

// ---------------------------------------------------------------------------
__device__ __forceinline__ uint32_t f2tf32(float x) {
    uint32_t r;
    asm("cvt.rna.tf32.f32 %0, %1;" : "=r"(r) : "f"(x));
    return r;
}

__device__ __forceinline__ void mma_tf32(float& d0, float& d1, float& d2,
                                         float& d3, uint32_t a0, uint32_t a1,
                                         uint32_t a2, uint32_t a3, uint32_t b0,
                                         uint32_t b1) {
    asm volatile(
        "mma.sync.aligned.m16n8k8.row.col.f32.tf32.tf32.f32 "
        "{%0,%1,%2,%3}, {%4,%5,%6,%7}, {%8,%9}, {%0,%1,%2,%3};"
        : "+f"(d0), "+f"(d1), "+f"(d2), "+f"(d3)
        : "r"(a0), "r"(a1), "r"(a2), "r"(a3), "r"(b0), "r"(b1));
}

// ===========================================================================
// tf32 mma.sync NT-GEMM: CTA tile 128x256x16, 8 warps (2m x 4n),
// warp tile 64x64 (mt4 x nt8). Double-buffered smem + register prefetch.
// C = A (M x K) @ W^T. Grid: (M/128, N/256).
// ===========================================================================
#define SP 20
#define NKIT (DMODEL / 16)          // 64
#define GA_SZ (128 * SP)            // uint32 per A buffer
#define GW_SZ (256 * SP)            // uint32 per W buffer
#define GEMM_SMEM ((2 * (GA_SZ + GW_SZ)) * (int)sizeof(uint32_t))  // 61440 B

template <int SCATTER>
__global__ void __launch_bounds__(256)
gemm_mma(const float* __restrict__ A, const float* __restrict__ W,
         float* __restrict__ C)
{
    extern __shared__ uint32_t gsm[];
    uint32_t* As = gsm;                     // [2][128*SP]
    uint32_t* Ws = gsm + 2 * GA_SZ;         // [2][256*SP]

    const int tid = threadIdx.x;
    const int wid = tid >> 5;
    const int lane = tid & 31;
    const int wm = (wid >> 2) * 64;
    const int wn = (wid & 3) * 64;
    const int r = lane >> 2;
    const int c = lane & 3;
    const int m0 = blockIdx.x * 128;
    const int n0 = blockIdx.y * 256;

    const int grow = tid >> 2;              // 0..63
    const int gcol = (tid & 3) * 4;

    const float* Ag0 = A + (size_t)(m0 + grow) * DMODEL + gcol;
    const float* Ag1 = Ag0 + (size_t)64 * DMODEL;
    const float* Wg0 = W + (size_t)(n0 + grow) * DMODEL + gcol;
    const float* Wg1 = Wg0 + (size_t)64 * DMODEL;
    const float* Wg2 = Wg0 + (size_t)128 * DMODEL;
    const float* Wg3 = Wg0 + (size_t)192 * DMODEL;

    float acc[4][8][4];
#pragma unroll
    for (int i = 0; i < 4; i++)
#pragma unroll
        for (int j = 0; j < 8; j++)
#pragma unroll
            for (int q = 0; q < 4; q++) acc[i][j][q] = 0.0f;

    float4 pa0, pa1, pw0, pw1, pw2, pw3;

    // prologue: tile 0 -> buffer 0
    pa0 = *(const float4*)(Ag0);
    pa1 = *(const float4*)(Ag1);
    pw0 = *(const float4*)(Wg0);
    pw1 = *(const float4*)(Wg1);
    pw2 = *(const float4*)(Wg2);
    pw3 = *(const float4*)(Wg3);
    {
        uint32_t* qa0 = As + grow * SP + gcol;
        uint32_t* qw0 = Ws + grow * SP + gcol;
        qa0[0] = f2tf32(pa0.x); qa0[1] = f2tf32(pa0.y);
        qa0[2] = f2tf32(pa0.z); qa0[3] = f2tf32(pa0.w);
        uint32_t* qa1 = qa0 + 64 * SP;
        qa1[0] = f2tf32(pa1.x); qa1[1] = f2tf32(pa1.y);
        qa1[2] = f2tf32(pa1.z); qa1[3] = f2tf32(pa1.w);
        qw0[0] = f2tf32(pw0.x); qw0[1] = f2tf32(pw0.y);
        qw0[2] = f2tf32(pw0.z); qw0[3] = f2tf32(pw0.w);
        uint32_t* qw1 = qw0 + 64 * SP;
        qw1[0] = f2tf32(pw1.x); qw1[1] = f2tf32(pw1.y);
        qw1[2] = f2tf32(pw1.z); qw1[3] = f2tf32(pw1.w);
        uint32_t* qw2 = qw0 + 128 * SP;
        qw2[0] = f2tf32(pw2.x); qw2[1] = f2tf32(pw2.y);
        qw2[2] = f2tf32(pw2.z); qw2[3] = f2tf32(pw2.w);
        uint32_t* qw3 = qw0 + 192 * SP;
        qw3[0] = f2tf32(pw3.x); qw3[1] = f2tf32(pw3.y);
        qw3[2] = f2tf32(pw3.z); qw3[3] = f2tf32(pw3.w);
    }
    __syncthreads();

    for (int it = 0; it < NKIT; it++) {
        const int buf = it & 1;
        const bool more = (it + 1) < NKIT;
        if (more) {
            const int k0 = (it + 1) * 16;
            pa0 = *(const float4*)(Ag0 + k0);
            pa1 = *(const float4*)(Ag1 + k0);
            pw0 = *(const float4*)(Wg0 + k0);
            pw1 = *(const float4*)(Wg1 + k0);
            pw2 = *(const float4*)(Wg2 + k0);
            pw3 = *(const float4*)(Wg3 + k0);
        }

        const uint32_t* Ab = As + buf * GA_SZ;
        const uint32_t* Wb = Ws + buf * GW_SZ;
#pragma unroll
        for (int ks = 0; ks < 2; ks++) {
            const int kc = ks * 8 + c;
            uint32_t af[4][4];
#pragma unroll
            for (int mt = 0; mt < 4; mt++) {
                const int m = wm + mt * 16;
                af[mt][0] = Ab[(m + r) * SP + kc];
                af[mt][1] = Ab[(m + r + 8) * SP + kc];
                af[mt][2] = Ab[(m + r) * SP + kc + 4];
                af[mt][3] = Ab[(m + r + 8) * SP + kc + 4];
            }
            uint32_t bf[8][2];
#pragma unroll
            for (int nt = 0; nt < 8; nt++) {
                const int n = wn + nt * 8 + r;
                bf[nt][0] = Wb[n * SP + kc];
                bf[nt][1] = Wb[n * SP + kc + 4];
            }
#pragma unroll
            for (int mt = 0; mt < 4; mt++)
#pragma unroll
                for (int nt = 0; nt < 8; nt++)
                    mma_tf32(acc[mt][nt][0], acc[mt][nt][1], acc[mt][nt][2],
                             acc[mt][nt][3], af[mt][0], af[mt][1], af[mt][2],
                             af[mt][3], bf[nt][0], bf[nt][1]);
        }

        if (more) {
            uint32_t* Anb = As + (buf ^ 1) * GA_SZ;
            uint32_t* Wnb = Ws + (buf ^ 1) * GW_SZ;
            uint32_t* qa0 = Anb + grow * SP + gcol;
            uint32_t* qw0 = Wnb + grow * SP + gcol;
            qa0[0] = f2tf32(pa0.x); qa0[1] = f2tf32(pa0.y);
            qa0[2] = f2tf32(pa0.z); qa0[3] = f2tf32(pa0.w);
            uint32_t* qa1 = qa0 + 64 * SP;
            qa1[0] = f2tf32(pa1.x); qa1[1] = f2tf32(pa1.y);
            qa1[2] = f2tf32(pa1.z); qa1[3] = f2tf32(pa1.w);
            qw0[0] = f2tf32(pw0.x); qw0[1] = f2tf32(pw0.y);
            qw0[2] = f2tf32(pw0.z); qw0[3] = f2tf32(pw0.w);
            uint32_t* qw1 = qw0 + 64 * SP;
            qw1[0] = f2tf32(pw1.x); qw1[1] = f2tf32(pw1.y);
            qw1[2] = f2tf32(pw1.z); qw1[3] = f2tf32(pw1.w);
            uint32_t* qw2 = qw0 + 128 * SP;
            qw2[0] = f2tf32(pw2.x); qw2[1] = f2tf32(pw2.y);
            qw2[2] = f2tf32(pw2.z); qw2[3] = f2tf32(pw2.w);
            uint32_t* qw3 = qw0 + 192 * SP;
            qw3[0] = f2tf32(pw3.x); qw3[1] = f2tf32(pw3.y);
            qw3[2] = f2tf32(pw3.z); qw3[3] = f2tf32(pw3.w);
            __syncthreads();
        }
    }

    // epilogue
#pragma unroll
    for (int mt = 0; mt < 4; mt++) {
#pragma unroll
        for (int half = 0; half < 2; half++) {
            const int mrow = m0 + wm + mt * 16 + r + half * 8;
#pragma unroll
            for (int nt = 0; nt < 8; nt++) {
                const int ncol = wn + nt * 8 + 2 * c;
                float* dst;
                if (SCATTER) {
                    const int bb = mrow >> 11;
                    const int ll = mrow & (LEN - 1);
                    const int hh = (n0 + ncol) >> 7;
                    const int dcol = ncol & 127;
                    dst = C + (((size_t)(hh * BATCH + bb) * LEN + ll) << 7) +
                          dcol;
                } else {
                    dst = C + (size_t)mrow * DMODEL + n0 + ncol;
                }
                *(float2*)dst =
                    make_float2(acc[mt][nt][half * 2], acc[mt][nt][half * 2 + 1]);
            }
        }
    }
}

// ===========================================================================
// Flash attention via mma.sync tf32 (unchanged from R4).
// ===========================================================================
#define ASP 132
#define BSP 68
#define SMA_Q 0
#define SMA_K (128 * ASP)
#define SMA_V (SMA_K + 64 * ASP)
#define SMA_P (SMA_V + 128 * BSP)
#define SMA_TOT (SMA_P + 128 * BSP)
#define SMEM_ATTN (SMA_TOT * (int)sizeof(uint32_t))

__global__ void __launch_bounds__(256)
attn_mma(const int* __restrict__ seq)
{
    extern __shared__ uint32_t sm[];
    uint32_t* Qs = sm + SMA_Q;
    uint32_t* Ks = sm + SMA_K;
    uint32_t* Vt = sm + SMA_V;
    uint32_t* Ps = sm + SMA_P;

    const int tid = threadIdx.x;
    const int wid = tid >> 5;
    const int lane = tid & 31;
    const int r = lane >> 2;
    const int c = lane & 3;
    const int qt = blockIdx.x, b = blockIdx.y, h = blockIdx.z;
    const int qbase = qt * 128;
    const int slen = seq[b];
    const int q0 = wid * 16;

    float* ctx = g_ctx + (size_t)b * LEN * DMODEL + (size_t)h * DHEAD;

    if (qbase >= slen) {
#pragma unroll
        for (int it = 0; it < 16; it++) {
            const int f = tid + it * 256;
            const int row = f >> 5;
            const int col = (f & 31) * 4;
            *(float4*)(ctx + (size_t)(qbase + row) * DMODEL + col) =
                make_float4(0.f, 0.f, 0.f, 0.f);
        }
        return;
    }

    const float* Qg = g_Q + (((size_t)h * BATCH + b) * LEN + qbase) * DHEAD;
    const float* Kg = g_K + ((size_t)h * BATCH + b) * LEN * DHEAD;
    const float* Vg = g_V + ((size_t)h * BATCH + b) * LEN * DHEAD;

    {
        const float scl = 0.08838834764831845f;
#pragma unroll
        for (int it = 0; it < 16; it++) {
            const int f = tid + it * 256;
            const int row = f >> 5;
            const int col = (f & 31) * 4;
            const float4 v = *(const float4*)(Qg + (size_t)row * DHEAD + col);
            uint32_t* p = Qs + row * ASP + col;
            p[0] = f2tf32(v.x * scl); p[1] = f2tf32(v.y * scl);
            p[2] = f2tf32(v.z * scl); p[3] = f2tf32(v.w * scl);
        }
    }
    __syncthreads();

    uint32_t qf[16][4];
#pragma unroll
    for (int ks = 0; ks < 16; ks++) {
        const int kc = ks * 8 + c;
        qf[ks][0] = Qs[(q0 + r) * ASP + kc];
        qf[ks][1] = Qs[(q0 + r + 8) * ASP + kc];
        qf[ks][2] = Qs[(q0 + r) * ASP + kc + 4];
        qf[ks][3] = Qs[(q0 + r + 8) * ASP + kc + 4];
    }

    float o[16][4];
#pragma unroll
    for (int nt = 0; nt < 16; nt++)
#pragma unroll
        for (int q = 0; q < 4; q++) o[nt][q] = 0.0f;
    float m0v = -1e30f, m1v = -1e30f, l0 = 0.0f, l1 = 0.0f;

    const int nkt = (slen + 63) >> 6;
    for (int kt = 0; kt < nkt; kt++) {
        const int kb = kt * 64;
        __syncthreads();

#pragma unroll
        for (int it = 0; it < 8; it++) {
            const int f = tid + it * 256;
            const int row = f >> 5;
            const int col = (f & 31) * 4;
            const float4 v =
                *(const float4*)(Kg + (size_t)(kb + row) * DHEAD + col);
            uint32_t* p = Ks + row * ASP + col;
            p[0] = f2tf32(v.x); p[1] = f2tf32(v.y);
            p[2] = f2tf32(v.z); p[3] = f2tf32(v.w);
        }
#pragma unroll
        for (int it = 0; it < 8; it++) {
            const int f = tid + it * 256;
            const int j = f >> 5;
            const int d = (f & 31) * 4;
            const float4 v =
                *(const float4*)(Vg + (size_t)(kb + j) * DHEAD + d);
            Vt[(d + 0) * BSP + j] = f2tf32(v.x);
            Vt[(d + 1) * BSP + j] = f2tf32(v.y);
            Vt[(d + 2) * BSP + j] = f2tf32(v.z);
            Vt[(d + 3) * BSP + j] = f2tf32(v.w);
        }
        __syncthreads();

        float s[8][4];
#pragma unroll
        for (int nt = 0; nt < 8; nt++)
#pragma unroll
            for (int q = 0; q < 4; q++) s[nt][q] = 0.0f;

#pragma unroll
        for (int ks = 0; ks < 16; ks++) {
            const int kc = ks * 8 + c;
            uint32_t bf[8][2];
#pragma unroll
            for (int nt = 0; nt < 8; nt++) {
                bf[nt][0] = Ks[(nt * 8 + r) * ASP + kc];
                bf[nt][1] = Ks[(nt * 8 + r) * ASP + kc + 4];
            }
#pragma unroll
            for (int nt = 0; nt < 8; nt++)
                mma_tf32(s[nt][0], s[nt][1], s[nt][2], s[nt][3],
                         qf[ks][0], qf[ks][1], qf[ks][2], qf[ks][3],
                         bf[nt][0], bf[nt][1]);
        }

#pragma unroll
        for (int nt = 0; nt < 8; nt++) {
            const int j0 = kb + nt * 8 + 2 * c;
            if (j0 >= slen)     { s[nt][0] = -1e30f; s[nt][2] = -1e30f; }
            if (j0 + 1 >= slen) { s[nt][1] = -1e30f; s[nt][3] = -1e30f; }
        }

        float mt0 = -1e30f, mt1 = -1e30f;
#pragma unroll
        for (int nt = 0; nt < 8; nt++) {
            mt0 = fmaxf(mt0, fmaxf(s[nt][0], s[nt][1]));
            mt1 = fmaxf(mt1, fmaxf(s[nt][2], s[nt][3]));
        }
        mt0 = fmaxf(mt0, __shfl_xor_sync(0xffffffffu, mt0, 1));
        mt0 = fmaxf(mt0, __shfl_xor_sync(0xffffffffu, mt0, 2));
        mt1 = fmaxf(mt1, __shfl_xor_sync(0xffffffffu, mt1, 1));
        mt1 = fmaxf(mt1, __shfl_xor_sync(0xffffffffu, mt1, 2));

        const float mn0 = fmaxf(m0v, mt0);
        const float mn1 = fmaxf(m1v, mt1);
        const float sc0 = __expf(m0v - mn0);
        const float sc1 = __expf(m1v - mn1);
        m0v = mn0; m1v = mn1;

        float rs0 = 0.0f, rs1 = 0.0f;
#pragma unroll
        for (int nt = 0; nt < 8; nt++) {
            const float p0 = __expf(s[nt][0] - mn0);
            const float p1 = __expf(s[nt][1] - mn0);
            const float p2 = __expf(s[nt][2] - mn1);
            const float p3 = __expf(s[nt][3] - mn1);
            rs0 += p0 + p1;
            rs1 += p2 + p3;
            uint32_t* pa = Ps + (q0 + r) * BSP + nt * 8 + 2 * c;
            pa[0] = f2tf32(p0); pa[1] = f2tf32(p1);
            uint32_t* pb = Ps + (q0 + r + 8) * BSP + nt * 8 + 2 * c;
            pb[0] = f2tf32(p2); pb[1] = f2tf32(p3);
        }
        rs0 += __shfl_xor_sync(0xffffffffu, rs0, 1);
        rs0 += __shfl_xor_sync(0xffffffffu, rs0, 2);
        rs1 += __shfl_xor_sync(0xffffffffu, rs1, 1);
        rs1 += __shfl_xor_sync(0xffffffffu, rs1, 2);
        l0 = l0 * sc0 + rs0;
        l1 = l1 * sc1 + rs1;

#pragma unroll
        for (int nt = 0; nt < 16; nt++) {
            o[nt][0] *= sc0; o[nt][1] *= sc0;
            o[nt][2] *= sc1; o[nt][3] *= sc1;
        }
        __syncwarp();

#pragma unroll
        for (int ks = 0; ks < 8; ks++) {
            const int kc = ks * 8 + c;
            uint32_t af[4];
            af[0] = Ps[(q0 + r) * BSP + kc];
            af[1] = Ps[(q0 + r + 8) * BSP + kc];
            af[2] = Ps[(q0 + r) * BSP + kc + 4];
            af[3] = Ps[(q0 + r + 8) * BSP + kc + 4];
#pragma unroll
            for (int nt = 0; nt < 16; nt++) {
                const uint32_t b0 = Vt[(nt * 8 + r) * BSP + kc];
                const uint32_t b1 = Vt[(nt * 8 + r) * BSP + kc + 4];
                mma_tf32(o[nt][0], o[nt][1], o[nt][2], o[nt][3],
                         af[0], af[1], af[2], af[3], b0, b1);
            }
        }
    }

    const int qr0 = qbase + q0 + r;
    const int qr1 = qr0 + 8;
    const float inv0 = (qr0 < slen) ? (1.0f / l0) : 0.0f;
    const float inv1 = (qr1 < slen) ? (1.0f / l1) : 0.0f;
#pragma unroll
    for (int nt = 0; nt < 16; nt++) {
        const int col = nt * 8 + 2 * c;
        *(float2*)(ctx + (size_t)qr0 * DMODEL + col) =
            make_float2(o[nt][0] * inv0, o[nt][1] * inv0);
        *(float2*)(ctx + (size_t)qr1 * DMODEL + col) =
            make_float2(o[nt][2] * inv1, o[nt][3] * inv1);
    }
}

// ===========================================================================
extern "C" void kernel_launch(void* const* d_in, const int* in_sizes, int n_in,
                              void* d_out, int out_size)
{
    (void)in_sizes; (void)n_in; (void)out_size;
    const float* queries = (const float*)d_in[0];
    const float* keys    = (const float*)d_in[1];
    const int*   seqlen  = (const int*)d_in[2];
    const float* Wq      = (const float*)d_in[3];
    const float* Wk      = (const float*)d_in[4];
    const float* Wv      = (const float*)d_in[5];
    const float* Wo      = (const float*)d_in[6];
    float* out = (float*)d_out;

    void *pQ, *pK, *pV, *pC;
    cudaGetSymbolAddress(&pQ, g_Q);
    cudaGetSymbolAddress(&pK, g_K);
    cudaGetSymbolAddress(&pV, g_V);
    cudaGetSymbolAddress(&pC, g_ctx);

    cudaFuncSetAttribute(gemm_mma<1>,
                         cudaFuncAttributeMaxDynamicSharedMemorySize, GEMM_SMEM);
    cudaFuncSetAttribute(gemm_mma<0>,
                         cudaFuncAttributeMaxDynamicSharedMemorySize, GEMM_SMEM);
    cudaFuncSetAttribute(attn_mma,
                         cudaFuncAttributeMaxDynamicSharedMemorySize, SMEM_ATTN);

    const dim3 gg(MROWS / 128, DMODEL / 256);
    gemm_mma<1><<<gg, 256, GEMM_SMEM>>>(queries, Wq, (float*)pQ);
    gemm_mma<1><<<gg, 256, GEMM_SMEM>>>(keys,    Wk, (float*)pK);
    gemm_mma<1><<<gg, 256, GEMM_SMEM>>>(keys,    Wv, (float*)pV);

    attn_mma<<<dim3(LEN / 128, BATCH, NH), 256, SMEM_ATTN>>>(seqlen);

    gemm_mma<0><<<gg, 256, GEMM_SMEM>>>((const float*)pC, Wo, out);
}

// round 7
// speedup vs baseline: 1.8126x; 1.8126x over previous
#include <cuda_runtime.h>
#include <cstdint>
#include <math.h>

#define BATCH 4
#define LEN 2048
#define DMODEL 1024
#define NH 8
#define DHEAD 128
#define MROWS (BATCH * LEN)

// g_Q/g_K/g_V hold tf32-rounded (rna) fp32 values; g_Q pre-scaled by 1/sqrt(128)
__device__ float g_Q[NH * BATCH * LEN * DHEAD];    // [h][b][l][d]
__device__ float g_K[NH * BATCH * LEN * DHEAD];
__device__ float g_V[NH * BATCH * LEN * DHEAD];
__device__ float g_ctx[BATCH * LEN * DMODEL];      // [b][l][h*128+d]

#define QSCL 0.08838834764831845f

// ---------------------------------------------------------------------------
__device__ __forceinline__ uint32_t f2tf32(float x) {
    uint32_t r;
    asm("cvt.rna.tf32.f32 %0, %1;" : "=r"(r) : "f"(x));
    return r;
}

__device__ __forceinline__ void mma_tf32(float& d0, float& d1, float& d2,
                                         float& d3, uint32_t a0, uint32_t a1,
                                         uint32_t a2, uint32_t a3, uint32_t b0,
                                         uint32_t b1) {
    asm volatile(
        "mma.sync.aligned.m16n8k8.row.col.f32.tf32.tf32.f32 "
        "{%0,%1,%2,%3}, {%4,%5,%6,%7}, {%8,%9}, {%0,%1,%2,%3};"
        : "+f"(d0), "+f"(d1), "+f"(d2), "+f"(d3)
        : "r"(a0), "r"(a1), "r"(a2), "r"(a3), "r"(b0), "r"(b1));
}

__device__ __forceinline__ uint32_t smem_u32(const void* p) {
    uint32_t a;
    asm("{ .reg .u64 t; cvta.to.shared.u64 t, %1; cvt.u32.u64 %0, t; }"
        : "=r"(a) : "l"(p));
    return a;
}

#define CP_ASYNC16(dst_u32, src_ptr)                                          \
    asm volatile("cp.async.cg.shared.global [%0], [%1], 16;"                  \
                 :: "r"(dst_u32), "l"(src_ptr) : "memory")
#define CP_COMMIT() asm volatile("cp.async.commit_group;" ::: "memory")
#define CP_WAIT(n)  asm volatile("cp.async.wait_group %0;" :: "n"(n) : "memory")

// ===========================================================================
// tf32 mma.sync NT-GEMM (R4 version — single-buffered, measured best).
// MODE 0: plain row-major fp32 out. MODE 1: scatter + tf32-round.
// MODE 2: scatter + scale by QSCL + tf32-round.
// ===========================================================================
#define SP 20

template <int MODE>
__global__ void __launch_bounds__(256)
gemm_mma(const float* __restrict__ A, const float* __restrict__ W,
         float* __restrict__ C)
{
    __shared__ uint32_t As[128 * SP];
    __shared__ uint32_t Ws[128 * SP];

    const int tid = threadIdx.x;
    const int wid = tid >> 5;
    const int lane = tid & 31;
    const int wm = (wid >> 2) * 64;
    const int wn = (wid & 3) * 32;
    const int r = lane >> 2;
    const int c = lane & 3;
    const int m0 = blockIdx.x * 128;
    const int n0 = blockIdx.y * 128;

    const int grow0 = tid >> 2;
    const int grow1 = grow0 + 64;
    const int gcol = (tid & 3) * 4;

    const float* Ag0 = A + (size_t)(m0 + grow0) * DMODEL + gcol;
    const float* Ag1 = A + (size_t)(m0 + grow1) * DMODEL + gcol;
    const float* Wg0 = W + (size_t)(n0 + grow0) * DMODEL + gcol;
    const float* Wg1 = W + (size_t)(n0 + grow1) * DMODEL + gcol;

    float acc[4][4][4];
#pragma unroll
    for (int i = 0; i < 4; i++)
#pragma unroll
        for (int j = 0; j < 4; j++)
#pragma unroll
            for (int q = 0; q < 4; q++) acc[i][j][q] = 0.0f;

    for (int k0 = 0; k0 < DMODEL; k0 += 16) {
        const float4 a0 = *(const float4*)(Ag0 + k0);
        const float4 a1 = *(const float4*)(Ag1 + k0);
        const float4 w0 = *(const float4*)(Wg0 + k0);
        const float4 w1 = *(const float4*)(Wg1 + k0);
        __syncthreads();
        {
            uint32_t* pa0 = As + grow0 * SP + gcol;
            uint32_t* pa1 = As + grow1 * SP + gcol;
            uint32_t* pw0 = Ws + grow0 * SP + gcol;
            uint32_t* pw1 = Ws + grow1 * SP + gcol;
            pa0[0] = f2tf32(a0.x); pa0[1] = f2tf32(a0.y);
            pa0[2] = f2tf32(a0.z); pa0[3] = f2tf32(a0.w);
            pa1[0] = f2tf32(a1.x); pa1[1] = f2tf32(a1.y);
            pa1[2] = f2tf32(a1.z); pa1[3] = f2tf32(a1.w);
            pw0[0] = f2tf32(w0.x); pw0[1] = f2tf32(w0.y);
            pw0[2] = f2tf32(w0.z); pw0[3] = f2tf32(w0.w);
            pw1[0] = f2tf32(w1.x); pw1[1] = f2tf32(w1.y);
            pw1[2] = f2tf32(w1.z); pw1[3] = f2tf32(w1.w);
        }
        __syncthreads();

#pragma unroll
        for (int ks = 0; ks < 2; ks++) {
            const int kc = ks * 8 + c;
            uint32_t af[4][4];
#pragma unroll
            for (int mt = 0; mt < 4; mt++) {
                const int m = wm + mt * 16;
                af[mt][0] = As[(m + r) * SP + kc];
                af[mt][1] = As[(m + r + 8) * SP + kc];
                af[mt][2] = As[(m + r) * SP + kc + 4];
                af[mt][3] = As[(m + r + 8) * SP + kc + 4];
            }
            uint32_t bf[4][2];
#pragma unroll
            for (int nt = 0; nt < 4; nt++) {
                const int n = wn + nt * 8 + r;
                bf[nt][0] = Ws[n * SP + kc];
                bf[nt][1] = Ws[n * SP + kc + 4];
            }
#pragma unroll
            for (int mt = 0; mt < 4; mt++)
#pragma unroll
                for (int nt = 0; nt < 4; nt++)
                    mma_tf32(acc[mt][nt][0], acc[mt][nt][1], acc[mt][nt][2],
                             acc[mt][nt][3], af[mt][0], af[mt][1], af[mt][2],
                             af[mt][3], bf[nt][0], bf[nt][1]);
        }
    }

#pragma unroll
    for (int mt = 0; mt < 4; mt++) {
#pragma unroll
        for (int half = 0; half < 2; half++) {
            const int mrow = m0 + wm + mt * 16 + r + half * 8;
            float* dst;
            if (MODE >= 1) {
                const int bb = mrow >> 11;
                const int ll = mrow & (LEN - 1);
                const int hh = n0 >> 7;
                dst = C + (((size_t)(hh * BATCH + bb) * LEN + ll) << 7);
            } else {
                dst = C + (size_t)mrow * DMODEL + n0;
            }
#pragma unroll
            for (int nt = 0; nt < 4; nt++) {
                const int ncol = wn + nt * 8 + 2 * c;
                float v0 = acc[mt][nt][half * 2];
                float v1 = acc[mt][nt][half * 2 + 1];
                if (MODE == 2) { v0 *= QSCL; v1 *= QSCL; }
                if (MODE >= 1) {
                    v0 = __uint_as_float(f2tf32(v0));
                    v1 = __uint_as_float(f2tf32(v1));
                }
                *(float2*)(dst + ncol) = make_float2(v0, v1);
            }
        }
    }
}

// ===========================================================================
// Flash attention, mma.sync tf32, cp.async double-buffered K/V stages.
// Inputs already tf32-rounded (and Q pre-scaled) by projection epilogues.
// ===========================================================================
#define KP 132               // K/Q pitch: banks (4r+c), conflict-free
#define VP 136               // V pitch (natural [j][d]): banks (8c+r), c-f
#define PSP 68               // P pitch
#define STG (64 * KP + 64 * VP)      // 17152 u32 per stage (K then V)
#define SMA_PS (2 * STG)             // 34304
#define SMA_TOT (SMA_PS + 128 * PSP) // 43008 u32
#define SMEM_ATTN (SMA_TOT * (int)sizeof(uint32_t))   // 172032 B

__global__ void __launch_bounds__(256)
attn_mma(const int* __restrict__ seq)
{
    extern __shared__ uint32_t sm[];
    const uint32_t sb = smem_u32(sm);
    uint32_t* Ps = sm + SMA_PS;

    const int tid = threadIdx.x;
    const int wid = tid >> 5;
    const int lane = tid & 31;
    const int r = lane >> 2;
    const int c = lane & 3;
    const int qt = blockIdx.x, b = blockIdx.y, h = blockIdx.z;
    const int qbase = qt * 128;
    const int slen = seq[b];
    const int q0 = wid * 16;

    float* ctx = g_ctx + (size_t)b * LEN * DMODEL + (size_t)h * DHEAD;

    if (qbase >= slen) {
#pragma unroll
        for (int it = 0; it < 16; it++) {
            const int f = tid + it * 256;
            const int row = f >> 5;
            const int col = (f & 31) * 4;
            *(float4*)(ctx + (size_t)(qbase + row) * DMODEL + col) =
                make_float4(0.f, 0.f, 0.f, 0.f);
        }
        return;
    }

    const float* Qg = g_Q + (((size_t)h * BATCH + b) * LEN + qbase) * DHEAD;
    const float* Kg = g_K + ((size_t)h * BATCH + b) * LEN * DHEAD;
    const float* Vg = g_V + ((size_t)h * BATCH + b) * LEN * DHEAD;

    const int nkt = (slen + 63) >> 6;

    // ---- Q staging via cp.async into stage-0 area (aliased; pitch KP) ----
#pragma unroll
    for (int it = 0; it < 16; it++) {
        const int f = tid + it * 256;
        const int row = f >> 5;
        const int col = (f & 31) * 4;
        CP_ASYNC16(sb + (row * KP + col) * 4, Qg + (size_t)row * DHEAD + col);
    }
    CP_COMMIT();
    CP_WAIT(0);
    __syncthreads();

    uint32_t qf[16][4];
#pragma unroll
    for (int ks = 0; ks < 16; ks++) {
        const int kc = ks * 8 + c;
        qf[ks][0] = sm[(q0 + r) * KP + kc];
        qf[ks][1] = sm[(q0 + r + 8) * KP + kc];
        qf[ks][2] = sm[(q0 + r) * KP + kc + 4];
        qf[ks][3] = sm[(q0 + r + 8) * KP + kc + 4];
    }
    __syncthreads();   // everyone hoisted before stage-0 overwrite

    // thread's fixed share of a K/V stage load: 8 chunks each
    const int lrow = tid >> 5;          // 0..7 base row
    const int lcol = (lane & 31) * 4;   // 0..124 step 4

    // prologue: issue stage 0 and stage 1
#pragma unroll 1
    for (int pre = 0; pre < 2; pre++) {
        if (pre < nkt) {
            const int kb = pre * 64;
            const uint32_t kbase = sb + (pre * STG) * 4;
            const uint32_t vbase = sb + (pre * STG + 64 * KP) * 4;
#pragma unroll
            for (int it = 0; it < 8; it++) {
                const int row = lrow + it * 8;
                CP_ASYNC16(kbase + (row * KP + lcol) * 4,
                           Kg + (size_t)(kb + row) * DHEAD + lcol);
                CP_ASYNC16(vbase + (row * VP + lcol) * 4,
                           Vg + (size_t)(kb + row) * DHEAD + lcol);
            }
        }
        CP_COMMIT();
    }

    float o[16][4];
#pragma unroll
    for (int nt = 0; nt < 16; nt++)
#pragma unroll
        for (int q = 0; q < 4; q++) o[nt][q] = 0.0f;
    float m0v = -1e30f, m1v = -1e30f, l0 = 0.0f, l1 = 0.0f;

    for (int kt = 0; kt < nkt; kt++) {
        const int kb = kt * 64;
        const int stg = kt & 1;
        const uint32_t* Ks = sm + stg * STG;
        const uint32_t* Vs = sm + stg * STG + 64 * KP;

        CP_WAIT(1);        // stage kt complete (kt+1 may be in flight)
        __syncthreads();

        // S = Q K^T
        float s[8][4];
#pragma unroll
        for (int nt = 0; nt < 8; nt++)
#pragma unroll
            for (int q = 0; q < 4; q++) s[nt][q] = 0.0f;

#pragma unroll
        for (int ks = 0; ks < 16; ks++) {
            const int kc = ks * 8 + c;
            uint32_t bf[8][2];
#pragma unroll
            for (int nt = 0; nt < 8; nt++) {
                bf[nt][0] = Ks[(nt * 8 + r) * KP + kc];
                bf[nt][1] = Ks[(nt * 8 + r) * KP + kc + 4];
            }
#pragma unroll
            for (int nt = 0; nt < 8; nt++)
                mma_tf32(s[nt][0], s[nt][1], s[nt][2], s[nt][3],
                         qf[ks][0], qf[ks][1], qf[ks][2], qf[ks][3],
                         bf[nt][0], bf[nt][1]);
        }

        // key mask
#pragma unroll
        for (int nt = 0; nt < 8; nt++) {
            const int j0 = kb + nt * 8 + 2 * c;
            if (j0 >= slen)     { s[nt][0] = -1e30f; s[nt][2] = -1e30f; }
            if (j0 + 1 >= slen) { s[nt][1] = -1e30f; s[nt][3] = -1e30f; }
        }

        // online softmax
        float mt0 = -1e30f, mt1 = -1e30f;
#pragma unroll
        for (int nt = 0; nt < 8; nt++) {
            mt0 = fmaxf(mt0, fmaxf(s[nt][0], s[nt][1]));
            mt1 = fmaxf(mt1, fmaxf(s[nt][2], s[nt][3]));
        }
        mt0 = fmaxf(mt0, __shfl_xor_sync(0xffffffffu, mt0, 1));
        mt0 = fmaxf(mt0, __shfl_xor_sync(0xffffffffu, mt0, 2));
        mt1 = fmaxf(mt1, __shfl_xor_sync(0xffffffffu, mt1, 1));
        mt1 = fmaxf(mt1, __shfl_xor_sync(0xffffffffu, mt1, 2));

        const float mn0 = fmaxf(m0v, mt0);
        const float mn1 = fmaxf(m1v, mt1);
        const float sc0 = __expf(m0v - mn0);
        const float sc1 = __expf(m1v - mn1);
        m0v = mn0; m1v = mn1;

        float rs0 = 0.0f, rs1 = 0.0f;
#pragma unroll
        for (int nt = 0; nt < 8; nt++) {
            const float p0 = __expf(s[nt][0] - mn0);
            const float p1 = __expf(s[nt][1] - mn0);
            const float p2 = __expf(s[nt][2] - mn1);
            const float p3 = __expf(s[nt][3] - mn1);
            rs0 += p0 + p1;
            rs1 += p2 + p3;
            uint32_t* pa = Ps + (q0 + r) * PSP + nt * 8 + 2 * c;
            pa[0] = f2tf32(p0); pa[1] = f2tf32(p1);
            uint32_t* pb = Ps + (q0 + r + 8) * PSP + nt * 8 + 2 * c;
            pb[0] = f2tf32(p2); pb[1] = f2tf32(p3);
        }
        rs0 += __shfl_xor_sync(0xffffffffu, rs0, 1);
        rs0 += __shfl_xor_sync(0xffffffffu, rs0, 2);
        rs1 += __shfl_xor_sync(0xffffffffu, rs1, 1);
        rs1 += __shfl_xor_sync(0xffffffffu, rs1, 2);
        l0 = l0 * sc0 + rs0;
        l1 = l1 * sc1 + rs1;

#pragma unroll
        for (int nt = 0; nt < 16; nt++) {
            o[nt][0] *= sc0; o[nt][1] *= sc0;
            o[nt][2] *= sc1; o[nt][3] *= sc1;
        }
        __syncwarp();

        // O += P @ V   (V natural [j][d]; B frag: b0=Vs[kc*VP + n+r])
#pragma unroll
        for (int ks = 0; ks < 8; ks++) {
            const int kc = ks * 8 + c;
            uint32_t af[4];
            af[0] = Ps[(q0 + r) * PSP + kc];
            af[1] = Ps[(q0 + r + 8) * PSP + kc];
            af[2] = Ps[(q0 + r) * PSP + kc + 4];
            af[3] = Ps[(q0 + r + 8) * PSP + kc + 4];
#pragma unroll
            for (int nt = 0; nt < 16; nt++) {
                const uint32_t b0 = Vs[kc * VP + nt * 8 + r];
                const uint32_t b1 = Vs[(kc + 4) * VP + nt * 8 + r];
                mma_tf32(o[nt][0], o[nt][1], o[nt][2], o[nt][3],
                         af[0], af[1], af[2], af[3], b0, b1);
            }
        }

        __syncthreads();   // stage consumed by ALL warps before refill

        const int nxt = kt + 2;
        if (nxt < nkt) {
            const int kb2 = nxt * 64;
            const uint32_t kbase = sb + (stg * STG) * 4;
            const uint32_t vbase = sb + (stg * STG + 64 * KP) * 4;
#pragma unroll
            for (int it = 0; it < 8; it++) {
                const int row = lrow + it * 8;
                CP_ASYNC16(kbase + (row * KP + lcol) * 4,
                           Kg + (size_t)(kb2 + row) * DHEAD + lcol);
                CP_ASYNC16(vbase + (row * VP + lcol) * 4,
                           Vg + (size_t)(kb2 + row) * DHEAD + lcol);
            }
        }
        CP_COMMIT();       // commit every iter (empty groups complete at once)
    }

    // epilogue
    const int qr0 = qbase + q0 + r;
    const int qr1 = qr0 + 8;
    const float inv0 = (qr0 < slen) ? (1.0f / l0) : 0.0f;
    const float inv1 = (qr1 < slen) ? (1.0f / l1) : 0.0f;
#pragma unroll
    for (int nt = 0; nt < 16; nt++) {
        const int col = nt * 8 + 2 * c;
        *(float2*)(ctx + (size_t)qr0 * DMODEL + col) =
            make_float2(o[nt][0] * inv0, o[nt][1] * inv0);
        *(float2*)(ctx + (size_t)qr1 * DMODEL + col) =
            make_float2(o[nt][2] * inv1, o[nt][3] * inv1);
    }
}

// ===========================================================================
extern "C" void kernel_launch(void* const* d_in, const int* in_sizes, int n_in,
                              void* d_out, int out_size)
{
    (void)in_sizes; (void)n_in; (void)out_size;
    const float* queries = (const float*)d_in[0];
    const float* keys    = (const float*)d_in[1];
    const int*   seqlen  = (const int*)d_in[2];
    const float* Wq      = (const float*)d_in[3];
    const float* Wk      = (const float*)d_in[4];
    const float* Wv      = (const float*)d_in[5];
    const float* Wo      = (const float*)d_in[6];
    float* out = (float*)d_out;

    void *pQ, *pK, *pV, *pC;
    cudaGetSymbolAddress(&pQ, g_Q);
    cudaGetSymbolAddress(&pK, g_K);
    cudaGetSymbolAddress(&pV, g_V);
    cudaGetSymbolAddress(&pC, g_ctx);

    cudaFuncSetAttribute(attn_mma,
                         cudaFuncAttributeMaxDynamicSharedMemorySize,
                         SMEM_ATTN);

    const dim3 gg(MROWS / 128, DMODEL / 128);
    gemm_mma<2><<<gg, 256>>>(queries, Wq, (float*)pQ);
    gemm_mma<1><<<gg, 256>>>(keys,    Wk, (float*)pK);
    gemm_mma<1><<<gg, 256>>>(keys,    Wv, (float*)pV);

    attn_mma<<<dim3(LEN / 128, BATCH, NH), 256, SMEM_ATTN>>>(seqlen);

    gemm_mma<0><<<gg, 256>>>((const float*)pC, Wo, out);
}

// round 8
// speedup vs baseline: 2.6294x; 1.4506x over previous
#include <cuda_runtime.h>
#include <cuda_fp16.h>
#include <cstdint>
#include <math.h>

#define BATCH 4
#define LEN 2048
#define DMODEL 1024
#define NH 8
#define DHEAD 128
#define MROWS (BATCH * LEN)

// fp32 (tf32-rounded) attention operands; Q pre-scaled by 1/sqrt(128)
__device__ float g_Q[NH * BATCH * LEN * DHEAD];
__device__ float g_K[NH * BATCH * LEN * DHEAD];
__device__ float g_V[NH * BATCH * LEN * DHEAD];
// fp16 GEMM operands
__device__ __half g_hA[MROWS * DMODEL];        // queries fp16
__device__ __half g_hB[MROWS * DMODEL];        // keys fp16
__device__ __half g_hWq[DMODEL * DMODEL];
__device__ __half g_hWk[DMODEL * DMODEL];
__device__ __half g_hWv[DMODEL * DMODEL];
__device__ __half g_hWo[DMODEL * DMODEL];
__device__ __half g_ctx_h[BATCH * LEN * DMODEL];  // attention output, fp16

#define QSCL 0.08838834764831845f

// ---------------------------------------------------------------------------
__device__ __forceinline__ uint32_t f2tf32(float x) {
    uint32_t r;
    asm("cvt.rna.tf32.f32 %0, %1;" : "=r"(r) : "f"(x));
    return r;
}

__device__ __forceinline__ void mma_tf32(float& d0, float& d1, float& d2,
                                         float& d3, uint32_t a0, uint32_t a1,
                                         uint32_t a2, uint32_t a3, uint32_t b0,
                                         uint32_t b1) {
    asm volatile(
        "mma.sync.aligned.m16n8k8.row.col.f32.tf32.tf32.f32 "
        "{%0,%1,%2,%3}, {%4,%5,%6,%7}, {%8,%9}, {%0,%1,%2,%3};"
        : "+f"(d0), "+f"(d1), "+f"(d2), "+f"(d3)
        : "r"(a0), "r"(a1), "r"(a2), "r"(a3), "r"(b0), "r"(b1));
}

__device__ __forceinline__ void mma_f16(float& d0, float& d1, float& d2,
                                        float& d3, uint32_t a0, uint32_t a1,
                                        uint32_t a2, uint32_t a3, uint32_t b0,
                                        uint32_t b1) {
    asm volatile(
        "mma.sync.aligned.m16n8k16.row.col.f32.f16.f16.f32 "
        "{%0,%1,%2,%3}, {%4,%5,%6,%7}, {%8,%9}, {%0,%1,%2,%3};"
        : "+f"(d0), "+f"(d1), "+f"(d2), "+f"(d3)
        : "r"(a0), "r"(a1), "r"(a2), "r"(a3), "r"(b0), "r"(b1));
}

__device__ __forceinline__ uint32_t smem_u32(const void* p) {
    uint32_t a;
    asm("{ .reg .u64 t; cvta.to.shared.u64 t, %1; cvt.u32.u64 %0, t; }"
        : "=r"(a) : "l"(p));
    return a;
}

#define CP_ASYNC16(dst_u32, src_ptr)                                          \
    asm volatile("cp.async.cg.shared.global [%0], [%1], 16;"                  \
                 :: "r"(dst_u32), "l"(src_ptr) : "memory")
#define CP_COMMIT() asm volatile("cp.async.commit_group;" ::: "memory")
#define CP_WAIT(n)  asm volatile("cp.async.wait_group %0;" :: "n"(n) : "memory")

// ===========================================================================
// fp32 -> fp16 conversion (grid-stride over float4)
// ===========================================================================
__global__ void __launch_bounds__(256)
cvt_f32_f16(const float* __restrict__ src, __half* __restrict__ dst, int n4)
{
    const int stride = gridDim.x * blockDim.x;
    for (int i = blockIdx.x * blockDim.x + threadIdx.x; i < n4; i += stride) {
        const float4 v = *(const float4*)(src + i * 4);
        __half2* d = (__half2*)(dst + i * 4);
        d[0] = __floats2half2_rn(v.x, v.y);
        d[1] = __floats2half2_rn(v.z, v.w);
    }
}

// ===========================================================================
// fp16 mma.sync NT-GEMM: C[MxN] = A[MxK] @ W^T (both fp16, fp32 accumulate).
// CTA 128x128, BK=32, 8 warps (2m x 4n), warp tile 64x32.
// cp.async double-buffered stages; fragments on half2 (u32) columns.
// MODE 0: plain fp32 out. MODE 1: scatter + tf32-round. MODE 2: +QSCL.
// ===========================================================================
#define HSP 20                      // u32 pitch (16 data cols + 4 pad)
#define HSTG (128 * HSP)            // u32 per operand per stage (2560)
#define HNIT (DMODEL / 32)          // 32 iterations

template <int MODE>
__global__ void __launch_bounds__(256)
gemm_h(const __half* __restrict__ A, const __half* __restrict__ W,
       float* __restrict__ C)
{
    __shared__ uint32_t sh[2 * 2 * HSTG];   // [stage][A/W][128*HSP] = 40960 B
    const uint32_t sb = smem_u32(sh);

    const int tid = threadIdx.x;
    const int wid = tid >> 5;
    const int lane = tid & 31;
    const int wm = (wid >> 2) * 64;
    const int wn = (wid & 3) * 32;
    const int r = lane >> 2;
    const int c = lane & 3;
    const int m0 = blockIdx.x * 128;
    const int n0 = blockIdx.y * 128;

    // cp.async mapping: each thread: 2 x 16B in A slab + 2 x 16B in W slab
    const int lrow = tid >> 1;              // 0..127
    const int lch = (tid & 1) * 2;          // chunk 0 or 2 (two consecutive)

    const __half* Ag = A + (size_t)(m0 + lrow) * DMODEL + lch * 8;
    const __half* Wg = W + (size_t)(n0 + lrow) * DMODEL + lch * 8;
    const uint32_t dstA = sb + (lrow * HSP + lch * 4) * 4;
    const uint32_t dstW = sb + (HSTG + lrow * HSP + lch * 4) * 4;

    float acc[4][4][4];
#pragma unroll
    for (int i = 0; i < 4; i++)
#pragma unroll
        for (int j = 0; j < 4; j++)
#pragma unroll
            for (int q = 0; q < 4; q++) acc[i][j][q] = 0.0f;

    // prologue: stages 0,1
#pragma unroll
    for (int pre = 0; pre < 2; pre++) {
        const int k0 = pre * 32;
        const uint32_t so = pre * 2 * HSTG * 4;
        CP_ASYNC16(dstA + so, Ag + k0);
        CP_ASYNC16(dstA + so + 16, Ag + k0 + 8);
        CP_ASYNC16(dstW + so, Wg + k0);
        CP_ASYNC16(dstW + so + 16, Wg + k0 + 8);
        CP_COMMIT();
    }

    for (int it = 0; it < HNIT; it++) {
        const int stg = it & 1;
        const uint32_t* As = sh + stg * 2 * HSTG;
        const uint32_t* Ws = As + HSTG;

        CP_WAIT(1);
        __syncthreads();

#pragma unroll
        for (int ks = 0; ks < 2; ks++) {        // two k16 steps
            const int kc = ks * 8 + c;
            uint32_t af[4][4];
#pragma unroll
            for (int mt = 0; mt < 4; mt++) {
                const int m = wm + mt * 16;
                af[mt][0] = As[(m + r) * HSP + kc];
                af[mt][1] = As[(m + r + 8) * HSP + kc];
                af[mt][2] = As[(m + r) * HSP + kc + 4];
                af[mt][3] = As[(m + r + 8) * HSP + kc + 4];
            }
            uint32_t bf[4][2];
#pragma unroll
            for (int nt = 0; nt < 4; nt++) {
                const int n = wn + nt * 8 + r;
                bf[nt][0] = Ws[n * HSP + kc];
                bf[nt][1] = Ws[n * HSP + kc + 4];
            }
#pragma unroll
            for (int mt = 0; mt < 4; mt++)
#pragma unroll
                for (int nt = 0; nt < 4; nt++)
                    mma_f16(acc[mt][nt][0], acc[mt][nt][1], acc[mt][nt][2],
                            acc[mt][nt][3], af[mt][0], af[mt][1], af[mt][2],
                            af[mt][3], bf[nt][0], bf[nt][1]);
        }

        __syncthreads();
        const int nxt = it + 2;
        if (nxt < HNIT) {
            const int k0 = nxt * 32;
            const uint32_t so = stg * 2 * HSTG * 4;
            CP_ASYNC16(dstA + so, Ag + k0);
            CP_ASYNC16(dstA + so + 16, Ag + k0 + 8);
            CP_ASYNC16(dstW + so, Wg + k0);
            CP_ASYNC16(dstW + so + 16, Wg + k0 + 8);
        }
        CP_COMMIT();
    }

    // epilogue
#pragma unroll
    for (int mt = 0; mt < 4; mt++) {
#pragma unroll
        for (int half = 0; half < 2; half++) {
            const int mrow = m0 + wm + mt * 16 + r + half * 8;
            float* dst;
            if (MODE >= 1) {
                const int bb = mrow >> 11;
                const int ll = mrow & (LEN - 1);
                const int hh = n0 >> 7;
                dst = C + (((size_t)(hh * BATCH + bb) * LEN + ll) << 7);
            } else {
                dst = C + (size_t)mrow * DMODEL + n0;
            }
#pragma unroll
            for (int nt = 0; nt < 4; nt++) {
                const int ncol = wn + nt * 8 + 2 * c;
                float v0 = acc[mt][nt][half * 2];
                float v1 = acc[mt][nt][half * 2 + 1];
                if (MODE == 2) { v0 *= QSCL; v1 *= QSCL; }
                if (MODE >= 1) {
                    v0 = __uint_as_float(f2tf32(v0));
                    v1 = __uint_as_float(f2tf32(v1));
                }
                *(float2*)(dst + ncol) = make_float2(v0, v1);
            }
        }
    }
}

// ===========================================================================
// Flash attention (R7 version; epilogue now writes fp16 ctx).
// ===========================================================================
#define KP 132
#define VP 136
#define PSP 68
#define STG (64 * KP + 64 * VP)
#define SMA_PS (2 * STG)
#define SMA_TOT (SMA_PS + 128 * PSP)
#define SMEM_ATTN (SMA_TOT * (int)sizeof(uint32_t))

__global__ void __launch_bounds__(256)
attn_mma(const int* __restrict__ seq)
{
    extern __shared__ uint32_t sm[];
    const uint32_t sb = smem_u32(sm);
    uint32_t* Ps = sm + SMA_PS;

    const int tid = threadIdx.x;
    const int wid = tid >> 5;
    const int lane = tid & 31;
    const int r = lane >> 2;
    const int c = lane & 3;
    const int qt = blockIdx.x, b = blockIdx.y, h = blockIdx.z;
    const int qbase = qt * 128;
    const int slen = seq[b];
    const int q0 = wid * 16;

    __half* ctx = g_ctx_h + (size_t)b * LEN * DMODEL + (size_t)h * DHEAD;

    if (qbase >= slen) {
        // zero-fill 128 rows x 128 halves (uint4 = 8 halves)
#pragma unroll
        for (int it = 0; it < 8; it++) {
            const int f = tid + it * 256;
            const int row = f >> 4;
            const int cu = (f & 15) * 8;
            *(uint4*)(ctx + (size_t)(qbase + row) * DMODEL + cu) =
                make_uint4(0, 0, 0, 0);
        }
        return;
    }

    const float* Qg = g_Q + (((size_t)h * BATCH + b) * LEN + qbase) * DHEAD;
    const float* Kg = g_K + ((size_t)h * BATCH + b) * LEN * DHEAD;
    const float* Vg = g_V + ((size_t)h * BATCH + b) * LEN * DHEAD;

    const int nkt = (slen + 63) >> 6;

    // Q staging via cp.async into stage-0 area
#pragma unroll
    for (int it = 0; it < 16; it++) {
        const int f = tid + it * 256;
        const int row = f >> 5;
        const int col = (f & 31) * 4;
        CP_ASYNC16(sb + (row * KP + col) * 4, Qg + (size_t)row * DHEAD + col);
    }
    CP_COMMIT();
    CP_WAIT(0);
    __syncthreads();

    uint32_t qf[16][4];
#pragma unroll
    for (int ks = 0; ks < 16; ks++) {
        const int kc = ks * 8 + c;
        qf[ks][0] = sm[(q0 + r) * KP + kc];
        qf[ks][1] = sm[(q0 + r + 8) * KP + kc];
        qf[ks][2] = sm[(q0 + r) * KP + kc + 4];
        qf[ks][3] = sm[(q0 + r + 8) * KP + kc + 4];
    }
    __syncthreads();

    const int lrow = tid >> 5;
    const int lcol = (lane & 31) * 4;

#pragma unroll 1
    for (int pre = 0; pre < 2; pre++) {
        if (pre < nkt) {
            const int kb = pre * 64;
            const uint32_t kbase = sb + (pre * STG) * 4;
            const uint32_t vbase = sb + (pre * STG + 64 * KP) * 4;
#pragma unroll
            for (int it = 0; it < 8; it++) {
                const int row = lrow + it * 8;
                CP_ASYNC16(kbase + (row * KP + lcol) * 4,
                           Kg + (size_t)(kb + row) * DHEAD + lcol);
                CP_ASYNC16(vbase + (row * VP + lcol) * 4,
                           Vg + (size_t)(kb + row) * DHEAD + lcol);
            }
        }
        CP_COMMIT();
    }

    float o[16][4];
#pragma unroll
    for (int nt = 0; nt < 16; nt++)
#pragma unroll
        for (int q = 0; q < 4; q++) o[nt][q] = 0.0f;
    float m0v = -1e30f, m1v = -1e30f, l0 = 0.0f, l1 = 0.0f;

    for (int kt = 0; kt < nkt; kt++) {
        const int kb = kt * 64;
        const int stg = kt & 1;
        const uint32_t* Ks = sm + stg * STG;
        const uint32_t* Vs = sm + stg * STG + 64 * KP;

        CP_WAIT(1);
        __syncthreads();

        float s[8][4];
#pragma unroll
        for (int nt = 0; nt < 8; nt++)
#pragma unroll
            for (int q = 0; q < 4; q++) s[nt][q] = 0.0f;

#pragma unroll
        for (int ks = 0; ks < 16; ks++) {
            const int kc = ks * 8 + c;
            uint32_t bf[8][2];
#pragma unroll
            for (int nt = 0; nt < 8; nt++) {
                bf[nt][0] = Ks[(nt * 8 + r) * KP + kc];
                bf[nt][1] = Ks[(nt * 8 + r) * KP + kc + 4];
            }
#pragma unroll
            for (int nt = 0; nt < 8; nt++)
                mma_tf32(s[nt][0], s[nt][1], s[nt][2], s[nt][3],
                         qf[ks][0], qf[ks][1], qf[ks][2], qf[ks][3],
                         bf[nt][0], bf[nt][1]);
        }

#pragma unroll
        for (int nt = 0; nt < 8; nt++) {
            const int j0 = kb + nt * 8 + 2 * c;
            if (j0 >= slen)     { s[nt][0] = -1e30f; s[nt][2] = -1e30f; }
            if (j0 + 1 >= slen) { s[nt][1] = -1e30f; s[nt][3] = -1e30f; }
        }

        float mt0 = -1e30f, mt1 = -1e30f;
#pragma unroll
        for (int nt = 0; nt < 8; nt++) {
            mt0 = fmaxf(mt0, fmaxf(s[nt][0], s[nt][1]));
            mt1 = fmaxf(mt1, fmaxf(s[nt][2], s[nt][3]));
        }
        mt0 = fmaxf(mt0, __shfl_xor_sync(0xffffffffu, mt0, 1));
        mt0 = fmaxf(mt0, __shfl_xor_sync(0xffffffffu, mt0, 2));
        mt1 = fmaxf(mt1, __shfl_xor_sync(0xffffffffu, mt1, 1));
        mt1 = fmaxf(mt1, __shfl_xor_sync(0xffffffffu, mt1, 2));

        const float mn0 = fmaxf(m0v, mt0);
        const float mn1 = fmaxf(m1v, mt1);
        const float sc0 = __expf(m0v - mn0);
        const float sc1 = __expf(m1v - mn1);
        m0v = mn0; m1v = mn1;

        float rs0 = 0.0f, rs1 = 0.0f;
#pragma unroll
        for (int nt = 0; nt < 8; nt++) {
            const float p0 = __expf(s[nt][0] - mn0);
            const float p1 = __expf(s[nt][1] - mn0);
            const float p2 = __expf(s[nt][2] - mn1);
            const float p3 = __expf(s[nt][3] - mn1);
            rs0 += p0 + p1;
            rs1 += p2 + p3;
            uint32_t* pa = Ps + (q0 + r) * PSP + nt * 8 + 2 * c;
            pa[0] = f2tf32(p0); pa[1] = f2tf32(p1);
            uint32_t* pb = Ps + (q0 + r + 8) * PSP + nt * 8 + 2 * c;
            pb[0] = f2tf32(p2); pb[1] = f2tf32(p3);
        }
        rs0 += __shfl_xor_sync(0xffffffffu, rs0, 1);
        rs0 += __shfl_xor_sync(0xffffffffu, rs0, 2);
        rs1 += __shfl_xor_sync(0xffffffffu, rs1, 1);
        rs1 += __shfl_xor_sync(0xffffffffu, rs1, 2);
        l0 = l0 * sc0 + rs0;
        l1 = l1 * sc1 + rs1;

#pragma unroll
        for (int nt = 0; nt < 16; nt++) {
            o[nt][0] *= sc0; o[nt][1] *= sc0;
            o[nt][2] *= sc1; o[nt][3] *= sc1;
        }
        __syncwarp();

#pragma unroll
        for (int ks = 0; ks < 8; ks++) {
            const int kc = ks * 8 + c;
            uint32_t af[4];
            af[0] = Ps[(q0 + r) * PSP + kc];
            af[1] = Ps[(q0 + r + 8) * PSP + kc];
            af[2] = Ps[(q0 + r) * PSP + kc + 4];
            af[3] = Ps[(q0 + r + 8) * PSP + kc + 4];
#pragma unroll
            for (int nt = 0; nt < 16; nt++) {
                const uint32_t b0 = Vs[kc * VP + nt * 8 + r];
                const uint32_t b1 = Vs[(kc + 4) * VP + nt * 8 + r];
                mma_tf32(o[nt][0], o[nt][1], o[nt][2], o[nt][3],
                         af[0], af[1], af[2], af[3], b0, b1);
            }
        }

        __syncthreads();

        const int nxt = kt + 2;
        if (nxt < nkt) {
            const int kb2 = nxt * 64;
            const uint32_t kbase = sb + (stg * STG) * 4;
            const uint32_t vbase = sb + (stg * STG + 64 * KP) * 4;
#pragma unroll
            for (int it = 0; it < 8; it++) {
                const int row = lrow + it * 8;
                CP_ASYNC16(kbase + (row * KP + lcol) * 4,
                           Kg + (size_t)(kb2 + row) * DHEAD + lcol);
                CP_ASYNC16(vbase + (row * VP + lcol) * 4,
                           Vg + (size_t)(kb2 + row) * DHEAD + lcol);
            }
        }
        CP_COMMIT();
    }

    // epilogue: /l, query mask, store fp16 ctx
    const int qr0 = qbase + q0 + r;
    const int qr1 = qr0 + 8;
    const float inv0 = (qr0 < slen) ? (1.0f / l0) : 0.0f;
    const float inv1 = (qr1 < slen) ? (1.0f / l1) : 0.0f;
#pragma unroll
    for (int nt = 0; nt < 16; nt++) {
        const int col = nt * 8 + 2 * c;
        *(__half2*)(ctx + (size_t)qr0 * DMODEL + col) =
            __floats2half2_rn(o[nt][0] * inv0, o[nt][1] * inv0);
        *(__half2*)(ctx + (size_t)qr1 * DMODEL + col) =
            __floats2half2_rn(o[nt][2] * inv1, o[nt][3] * inv1);
    }
}

// ===========================================================================
extern "C" void kernel_launch(void* const* d_in, const int* in_sizes, int n_in,
                              void* d_out, int out_size)
{
    (void)in_sizes; (void)n_in; (void)out_size;
    const float* queries = (const float*)d_in[0];
    const float* keys    = (const float*)d_in[1];
    const int*   seqlen  = (const int*)d_in[2];
    const float* Wq      = (const float*)d_in[3];
    const float* Wk      = (const float*)d_in[4];
    const float* Wv      = (const float*)d_in[5];
    const float* Wo      = (const float*)d_in[6];
    float* out = (float*)d_out;

    void *pQ, *pK, *pV, *phA, *phB, *phWq, *phWk, *phWv, *phWo, *pCtxH;
    cudaGetSymbolAddress(&pQ, g_Q);
    cudaGetSymbolAddress(&pK, g_K);
    cudaGetSymbolAddress(&pV, g_V);
    cudaGetSymbolAddress(&phA, g_hA);
    cudaGetSymbolAddress(&phB, g_hB);
    cudaGetSymbolAddress(&phWq, g_hWq);
    cudaGetSymbolAddress(&phWk, g_hWk);
    cudaGetSymbolAddress(&phWv, g_hWv);
    cudaGetSymbolAddress(&phWo, g_hWo);
    cudaGetSymbolAddress(&pCtxH, g_ctx_h);

    cudaFuncSetAttribute(attn_mma,
                         cudaFuncAttributeMaxDynamicSharedMemorySize,
                         SMEM_ATTN);

    // fp32 -> fp16 conversions
    const int nBig4 = MROWS * DMODEL / 4;
    const int nW4 = DMODEL * DMODEL / 4;
    cvt_f32_f16<<<512, 256>>>(queries, (__half*)phA, nBig4);
    cvt_f32_f16<<<512, 256>>>(keys,    (__half*)phB, nBig4);
    cvt_f32_f16<<<256, 256>>>(Wq, (__half*)phWq, nW4);
    cvt_f32_f16<<<256, 256>>>(Wk, (__half*)phWk, nW4);
    cvt_f32_f16<<<256, 256>>>(Wv, (__half*)phWv, nW4);
    cvt_f32_f16<<<256, 256>>>(Wo, (__half*)phWo, nW4);

    const dim3 gg(MROWS / 128, DMODEL / 128);
    gemm_h<2><<<gg, 256>>>((const __half*)phA, (const __half*)phWq, (float*)pQ);
    gemm_h<1><<<gg, 256>>>((const __half*)phB, (const __half*)phWk, (float*)pK);
    gemm_h<1><<<gg, 256>>>((const __half*)phB, (const __half*)phWv, (float*)pV);

    attn_mma<<<dim3(LEN / 128, BATCH, NH), 256, SMEM_ATTN>>>(seqlen);

    gemm_h<0><<<gg, 256>>>((const __half*)pCtxH, (const __half*)phWo, out);
}

// round 9
// speedup vs baseline: 2.8841x; 1.0969x over previous
#include <cuda_runtime.h>
#include <cuda_fp16.h>
#include <cstdint>
#include <math.h>

#define BATCH 4
#define LEN 2048
#define DMODEL 1024
#define NH 8
#define DHEAD 128
#define MROWS (BATCH * LEN)

// fp16 GEMM operands
__device__ __half g_hA[MROWS * DMODEL];
__device__ __half g_hB[MROWS * DMODEL];
__device__ __half g_hWq[DMODEL * DMODEL];
__device__ __half g_hWk[DMODEL * DMODEL];
__device__ __half g_hWv[DMODEL * DMODEL];
__device__ __half g_hWo[DMODEL * DMODEL];
// fp16 attention operands
__device__ __half g_Qh[NH * BATCH * LEN * DHEAD];   // [h][b][l][d], pre-scaled
__device__ __half g_Kh[NH * BATCH * LEN * DHEAD];   // [h][b][l][d]
__device__ __half g_Vt[NH * BATCH * DHEAD * LEN];   // [h][b][d][l] transposed
__device__ __half g_ctx_h[BATCH * LEN * DMODEL];    // [b][l][h*128+d]

#define QSCL 0.08838834764831845f

// ---------------------------------------------------------------------------
__device__ __forceinline__ void mma_f16(float& d0, float& d1, float& d2,
                                        float& d3, uint32_t a0, uint32_t a1,
                                        uint32_t a2, uint32_t a3, uint32_t b0,
                                        uint32_t b1) {
    asm volatile(
        "mma.sync.aligned.m16n8k16.row.col.f32.f16.f16.f32 "
        "{%0,%1,%2,%3}, {%4,%5,%6,%7}, {%8,%9}, {%0,%1,%2,%3};"
        : "+f"(d0), "+f"(d1), "+f"(d2), "+f"(d3)
        : "r"(a0), "r"(a1), "r"(a2), "r"(a3), "r"(b0), "r"(b1));
}

__device__ __forceinline__ uint32_t smem_u32(const void* p) {
    uint32_t a;
    asm("{ .reg .u64 t; cvta.to.shared.u64 t, %1; cvt.u32.u64 %0, t; }"
        : "=r"(a) : "l"(p));
    return a;
}

__device__ __forceinline__ uint32_t pack_h2(float a, float b) {
    const __half2 h = __floats2half2_rn(a, b);
    return *(const uint32_t*)&h;
}

#define CP_ASYNC16(dst_u32, src_ptr)                                          \
    asm volatile("cp.async.cg.shared.global [%0], [%1], 16;"                  \
                 :: "r"(dst_u32), "l"(src_ptr) : "memory")
#define CP_COMMIT() asm volatile("cp.async.commit_group;" ::: "memory")
#define CP_WAIT(n)  asm volatile("cp.async.wait_group %0;" :: "n"(n) : "memory")

// ===========================================================================
// fp32 -> fp16 conversion
// ===========================================================================
__global__ void __launch_bounds__(256)
cvt_f32_f16(const float* __restrict__ src, __half* __restrict__ dst, int n4)
{
    const int stride = gridDim.x * blockDim.x;
    for (int i = blockIdx.x * blockDim.x + threadIdx.x; i < n4; i += stride) {
        const float4 v = *(const float4*)(src + i * 4);
        __half2* d = (__half2*)(dst + i * 4);
        d[0] = __floats2half2_rn(v.x, v.y);
        d[1] = __floats2half2_rn(v.z, v.w);
    }
}

// ===========================================================================
// fp16 mma.sync NT-GEMM (verified R8 core). Epilogue MODEs:
//  0: fp32 row-major out
//  1: fp16 scatter [h][b][l][d]            (K path)
//  2: fp16 scatter [h][b][l][d] * QSCL     (Q path)
//  3: fp16 TRANSPOSED scatter [h][b][d][l] (V path)
// ===========================================================================
#define HSP 20
#define HSTG (128 * HSP)
#define HNIT (DMODEL / 32)

template <int MODE>
__global__ void __launch_bounds__(256)
gemm_h(const __half* __restrict__ A, const __half* __restrict__ W, void* Cv)
{
    __shared__ uint32_t sh[2 * 2 * HSTG];
    const uint32_t sb = smem_u32(sh);

    const int tid = threadIdx.x;
    const int wid = tid >> 5;
    const int lane = tid & 31;
    const int wm = (wid >> 2) * 64;
    const int wn = (wid & 3) * 32;
    const int r = lane >> 2;
    const int c = lane & 3;
    const int m0 = blockIdx.x * 128;
    const int n0 = blockIdx.y * 128;

    const int lrow = tid >> 1;
    const int lch = (tid & 1) * 2;

    const __half* Ag = A + (size_t)(m0 + lrow) * DMODEL + lch * 8;
    const __half* Wg = W + (size_t)(n0 + lrow) * DMODEL + lch * 8;
    const uint32_t dstA = sb + (lrow * HSP + lch * 4) * 4;
    const uint32_t dstW = sb + (HSTG + lrow * HSP + lch * 4) * 4;

    float acc[4][4][4];
#pragma unroll
    for (int i = 0; i < 4; i++)
#pragma unroll
        for (int j = 0; j < 4; j++)
#pragma unroll
            for (int q = 0; q < 4; q++) acc[i][j][q] = 0.0f;

#pragma unroll
    for (int pre = 0; pre < 2; pre++) {
        const int k0 = pre * 32;
        const uint32_t so = pre * 2 * HSTG * 4;
        CP_ASYNC16(dstA + so, Ag + k0);
        CP_ASYNC16(dstA + so + 16, Ag + k0 + 8);
        CP_ASYNC16(dstW + so, Wg + k0);
        CP_ASYNC16(dstW + so + 16, Wg + k0 + 8);
        CP_COMMIT();
    }

    for (int it = 0; it < HNIT; it++) {
        const int stg = it & 1;
        const uint32_t* As = sh + stg * 2 * HSTG;
        const uint32_t* Ws = As + HSTG;

        CP_WAIT(1);
        __syncthreads();

#pragma unroll
        for (int ks = 0; ks < 2; ks++) {
            const int kc = ks * 8 + c;
            uint32_t af[4][4];
#pragma unroll
            for (int mt = 0; mt < 4; mt++) {
                const int m = wm + mt * 16;
                af[mt][0] = As[(m + r) * HSP + kc];
                af[mt][1] = As[(m + r + 8) * HSP + kc];
                af[mt][2] = As[(m + r) * HSP + kc + 4];
                af[mt][3] = As[(m + r + 8) * HSP + kc + 4];
            }
            uint32_t bf[4][2];
#pragma unroll
            for (int nt = 0; nt < 4; nt++) {
                const int n = wn + nt * 8 + r;
                bf[nt][0] = Ws[n * HSP + kc];
                bf[nt][1] = Ws[n * HSP + kc + 4];
            }
#pragma unroll
            for (int mt = 0; mt < 4; mt++)
#pragma unroll
                for (int nt = 0; nt < 4; nt++)
                    mma_f16(acc[mt][nt][0], acc[mt][nt][1], acc[mt][nt][2],
                            acc[mt][nt][3], af[mt][0], af[mt][1], af[mt][2],
                            af[mt][3], bf[nt][0], bf[nt][1]);
        }

        __syncthreads();
        const int nxt = it + 2;
        if (nxt < HNIT) {
            const int k0 = nxt * 32;
            const uint32_t so = stg * 2 * HSTG * 4;
            CP_ASYNC16(dstA + so, Ag + k0);
            CP_ASYNC16(dstA + so + 16, Ag + k0 + 8);
            CP_ASYNC16(dstW + so, Wg + k0);
            CP_ASYNC16(dstW + so + 16, Wg + k0 + 8);
        }
        CP_COMMIT();
    }

    // epilogue
#pragma unroll
    for (int mt = 0; mt < 4; mt++) {
#pragma unroll
        for (int half = 0; half < 2; half++) {
            const int mrow = m0 + wm + mt * 16 + r + half * 8;
            const int bb = mrow >> 11;
            const int ll = mrow & (LEN - 1);
            const int hh = n0 >> 7;
#pragma unroll
            for (int nt = 0; nt < 4; nt++) {
                const int ncol = wn + nt * 8 + 2 * c;
                float v0 = acc[mt][nt][half * 2];
                float v1 = acc[mt][nt][half * 2 + 1];
                if (MODE == 0) {
                    float* dst = (float*)Cv + (size_t)mrow * DMODEL + n0;
                    *(float2*)(dst + ncol) = make_float2(v0, v1);
                } else if (MODE == 1 || MODE == 2) {
                    if (MODE == 2) { v0 *= QSCL; v1 *= QSCL; }
                    __half* dst = (__half*)Cv +
                        (((size_t)(hh * BATCH + bb) * LEN + ll) << 7);
                    *(__half2*)(dst + ncol) = __floats2half2_rn(v0, v1);
                } else {   // MODE 3: transposed [h][b][d][l]
                    __half* base = (__half*)Cv +
                        (size_t)(hh * BATCH + bb) * DHEAD * LEN;
                    base[(size_t)ncol * LEN + ll] = __float2half_rn(v0);
                    base[(size_t)(ncol + 1) * LEN + ll] = __float2half_rn(v1);
                }
            }
        }
    }
}

// ===========================================================================
// Flash attention, all-fp16 mma (m16n8k16), cp.async double-buffered.
// K smem [j][d] half2-along-d (pitch 68 u32); Vt smem [d][j] half2-along-j
// (pitch 36 u32, fed by transposed g_Vt); P fp16 (pitch 36 u32).
// ===========================================================================
#define KP2 68                         // K/Q pitch (u32)
#define VP2 36                         // Vt / P pitch (u32)
#define STGH (64 * KP2 + 128 * VP2)    // 8960 u32 per stage
#define SMA_PS2 (2 * STGH)             // 17920
#define SMA_TOT2 (SMA_PS2 + 128 * VP2) // 22528 u32
#define SMEM_ATTN (SMA_TOT2 * (int)sizeof(uint32_t))   // 90112 B

__global__ void __launch_bounds__(256)
attn_mma(const int* __restrict__ seq)
{
    extern __shared__ uint32_t sm[];
    const uint32_t sb = smem_u32(sm);
    uint32_t* Ps = sm + SMA_PS2;

    const int tid = threadIdx.x;
    const int wid = tid >> 5;
    const int lane = tid & 31;
    const int r = lane >> 2;
    const int c = lane & 3;
    const int qt = blockIdx.x, b = blockIdx.y, h = blockIdx.z;
    const int qbase = qt * 128;
    const int slen = seq[b];
    const int q0 = wid * 16;

    __half* ctx = g_ctx_h + (size_t)b * LEN * DMODEL + (size_t)h * DHEAD;

    if (qbase >= slen) {
#pragma unroll
        for (int it = 0; it < 8; it++) {
            const int f = tid + it * 256;
            const int row = f >> 4;
            const int cu = (f & 15) * 8;
            *(uint4*)(ctx + (size_t)(qbase + row) * DMODEL + cu) =
                make_uint4(0, 0, 0, 0);
        }
        return;
    }

    const __half* Qg = g_Qh + (((size_t)h * BATCH + b) * LEN + qbase) * DHEAD;
    const __half* Kg = g_Kh + ((size_t)h * BATCH + b) * LEN * DHEAD;
    const __half* Vg = g_Vt + ((size_t)h * BATCH + b) * DHEAD * LEN;

    const int nkt = (slen + 63) >> 6;

    // ---- Q staging (aliases stage 0; pitch KP2) ----
#pragma unroll
    for (int it = 0; it < 8; it++) {
        const int f = tid + it * 256;
        const int row = f >> 4;               // 0..127
        const int ch = f & 15;                // 16B chunk (8 halves)
        CP_ASYNC16(sb + (row * KP2 + ch * 4) * 4,
                   Qg + (size_t)row * DHEAD + ch * 8);
    }
    CP_COMMIT();
    CP_WAIT(0);
    __syncthreads();

    uint32_t qf[8][4];
#pragma unroll
    for (int ks = 0; ks < 8; ks++) {
        const int kc = ks * 8 + c;
        qf[ks][0] = sm[(q0 + r) * KP2 + kc];
        qf[ks][1] = sm[(q0 + r + 8) * KP2 + kc];
        qf[ks][2] = sm[(q0 + r) * KP2 + kc + 4];
        qf[ks][3] = sm[(q0 + r + 8) * KP2 + kc + 4];
    }
    __syncthreads();

    // prologue: stages 0,1 (K: 64x16 chunks, V: 128x8 chunks, 8/thread)
#pragma unroll 1
    for (int pre = 0; pre < 2; pre++) {
        if (pre < nkt) {
            const int kb = pre * 64;
            const uint32_t kbase = sb + (pre * STGH) * 4;
            const uint32_t vbase = sb + (pre * STGH + 64 * KP2) * 4;
#pragma unroll
            for (int it = 0; it < 4; it++) {
                const int f = tid + it * 256;
                const int row = f >> 4;
                const int ch = f & 15;
                CP_ASYNC16(kbase + (row * KP2 + ch * 4) * 4,
                           Kg + (size_t)(kb + row) * DHEAD + ch * 8);
            }
#pragma unroll
            for (int it = 0; it < 4; it++) {
                const int f = tid + it * 256;
                const int d = f >> 3;
                const int ch = f & 7;
                CP_ASYNC16(vbase + (d * VP2 + ch * 4) * 4,
                           Vg + (size_t)d * LEN + kb + ch * 8);
            }
        }
        CP_COMMIT();
    }

    float o[16][4];
#pragma unroll
    for (int nt = 0; nt < 16; nt++)
#pragma unroll
        for (int q = 0; q < 4; q++) o[nt][q] = 0.0f;
    float m0v = -1e30f, m1v = -1e30f, l0 = 0.0f, l1 = 0.0f;

    for (int kt = 0; kt < nkt; kt++) {
        const int kb = kt * 64;
        const int stg = kt & 1;
        const uint32_t* Ks = sm + stg * STGH;
        const uint32_t* Vs = sm + stg * STGH + 64 * KP2;

        CP_WAIT(1);
        __syncthreads();

        // S = Q K^T  (8 k16-steps over d=128, 8 n-tiles over 64 keys)
        float s[8][4];
#pragma unroll
        for (int nt = 0; nt < 8; nt++)
#pragma unroll
            for (int q = 0; q < 4; q++) s[nt][q] = 0.0f;

#pragma unroll
        for (int ks = 0; ks < 8; ks++) {
            const int kc = ks * 8 + c;
            uint32_t bf[8][2];
#pragma unroll
            for (int nt = 0; nt < 8; nt++) {
                bf[nt][0] = Ks[(nt * 8 + r) * KP2 + kc];
                bf[nt][1] = Ks[(nt * 8 + r) * KP2 + kc + 4];
            }
#pragma unroll
            for (int nt = 0; nt < 8; nt++)
                mma_f16(s[nt][0], s[nt][1], s[nt][2], s[nt][3],
                        qf[ks][0], qf[ks][1], qf[ks][2], qf[ks][3],
                        bf[nt][0], bf[nt][1]);
        }

        // key mask
#pragma unroll
        for (int nt = 0; nt < 8; nt++) {
            const int j0 = kb + nt * 8 + 2 * c;
            if (j0 >= slen)     { s[nt][0] = -1e30f; s[nt][2] = -1e30f; }
            if (j0 + 1 >= slen) { s[nt][1] = -1e30f; s[nt][3] = -1e30f; }
        }

        // online softmax
        float mt0 = -1e30f, mt1 = -1e30f;
#pragma unroll
        for (int nt = 0; nt < 8; nt++) {
            mt0 = fmaxf(mt0, fmaxf(s[nt][0], s[nt][1]));
            mt1 = fmaxf(mt1, fmaxf(s[nt][2], s[nt][3]));
        }
        mt0 = fmaxf(mt0, __shfl_xor_sync(0xffffffffu, mt0, 1));
        mt0 = fmaxf(mt0, __shfl_xor_sync(0xffffffffu, mt0, 2));
        mt1 = fmaxf(mt1, __shfl_xor_sync(0xffffffffu, mt1, 1));
        mt1 = fmaxf(mt1, __shfl_xor_sync(0xffffffffu, mt1, 2));

        const float mn0 = fmaxf(m0v, mt0);
        const float mn1 = fmaxf(m1v, mt1);
        const float sc0 = __expf(m0v - mn0);
        const float sc1 = __expf(m1v - mn1);
        m0v = mn0; m1v = mn1;

        float rs0 = 0.0f, rs1 = 0.0f;
#pragma unroll
        for (int nt = 0; nt < 8; nt++) {
            const float p0 = __expf(s[nt][0] - mn0);
            const float p1 = __expf(s[nt][1] - mn0);
            const float p2 = __expf(s[nt][2] - mn1);
            const float p3 = __expf(s[nt][3] - mn1);
            rs0 += p0 + p1;
            rs1 += p2 + p3;
            Ps[(q0 + r) * VP2 + nt * 4 + c] = pack_h2(p0, p1);
            Ps[(q0 + r + 8) * VP2 + nt * 4 + c] = pack_h2(p2, p3);
        }
        rs0 += __shfl_xor_sync(0xffffffffu, rs0, 1);
        rs0 += __shfl_xor_sync(0xffffffffu, rs0, 2);
        rs1 += __shfl_xor_sync(0xffffffffu, rs1, 1);
        rs1 += __shfl_xor_sync(0xffffffffu, rs1, 2);
        l0 = l0 * sc0 + rs0;
        l1 = l1 * sc1 + rs1;

#pragma unroll
        for (int nt = 0; nt < 16; nt++) {
            o[nt][0] *= sc0; o[nt][1] *= sc0;
            o[nt][2] *= sc1; o[nt][3] *= sc1;
        }
        __syncwarp();

        // O += P @ V  (4 k16-steps over 64 keys, 16 n-tiles over d=128)
#pragma unroll
        for (int ks = 0; ks < 4; ks++) {
            const int kc = ks * 8 + c;
            uint32_t af[4];
            af[0] = Ps[(q0 + r) * VP2 + kc];
            af[1] = Ps[(q0 + r + 8) * VP2 + kc];
            af[2] = Ps[(q0 + r) * VP2 + kc + 4];
            af[3] = Ps[(q0 + r + 8) * VP2 + kc + 4];
#pragma unroll
            for (int nt = 0; nt < 16; nt++) {
                const uint32_t b0 = Vs[(nt * 8 + r) * VP2 + kc];
                const uint32_t b1 = Vs[(nt * 8 + r) * VP2 + kc + 4];
                mma_f16(o[nt][0], o[nt][1], o[nt][2], o[nt][3],
                        af[0], af[1], af[2], af[3], b0, b1);
            }
        }

        __syncthreads();

        const int nxt = kt + 2;
        if (nxt < nkt) {
            const int kb2 = nxt * 64;
            const uint32_t kbase = sb + (stg * STGH) * 4;
            const uint32_t vbase = sb + (stg * STGH + 64 * KP2) * 4;
#pragma unroll
            for (int it = 0; it < 4; it++) {
                const int f = tid + it * 256;
                const int row = f >> 4;
                const int ch = f & 15;
                CP_ASYNC16(kbase + (row * KP2 + ch * 4) * 4,
                           Kg + (size_t)(kb2 + row) * DHEAD + ch * 8);
            }
#pragma unroll
            for (int it = 0; it < 4; it++) {
                const int f = tid + it * 256;
                const int d = f >> 3;
                const int ch = f & 7;
                CP_ASYNC16(vbase + (d * VP2 + ch * 4) * 4,
                           Vg + (size_t)d * LEN + kb2 + ch * 8);
            }
        }
        CP_COMMIT();
    }

    // epilogue
    const int qr0 = qbase + q0 + r;
    const int qr1 = qr0 + 8;
    const float inv0 = (qr0 < slen) ? (1.0f / l0) : 0.0f;
    const float inv1 = (qr1 < slen) ? (1.0f / l1) : 0.0f;
#pragma unroll
    for (int nt = 0; nt < 16; nt++) {
        const int col = nt * 8 + 2 * c;
        *(__half2*)(ctx + (size_t)qr0 * DMODEL + col) =
            __floats2half2_rn(o[nt][0] * inv0, o[nt][1] * inv0);
        *(__half2*)(ctx + (size_t)qr1 * DMODEL + col) =
            __floats2half2_rn(o[nt][2] * inv1, o[nt][3] * inv1);
    }
}

// ===========================================================================
extern "C" void kernel_launch(void* const* d_in, const int* in_sizes, int n_in,
                              void* d_out, int out_size)
{
    (void)in_sizes; (void)n_in; (void)out_size;
    const float* queries = (const float*)d_in[0];
    const float* keys    = (const float*)d_in[1];
    const int*   seqlen  = (const int*)d_in[2];
    const float* Wq      = (const float*)d_in[3];
    const float* Wk      = (const float*)d_in[4];
    const float* Wv      = (const float*)d_in[5];
    const float* Wo      = (const float*)d_in[6];
    float* out = (float*)d_out;

    void *phA, *phB, *phWq, *phWk, *phWv, *phWo, *pQh, *pKh, *pVt, *pCtxH;
    cudaGetSymbolAddress(&phA, g_hA);
    cudaGetSymbolAddress(&phB, g_hB);
    cudaGetSymbolAddress(&phWq, g_hWq);
    cudaGetSymbolAddress(&phWk, g_hWk);
    cudaGetSymbolAddress(&phWv, g_hWv);
    cudaGetSymbolAddress(&phWo, g_hWo);
    cudaGetSymbolAddress(&pQh, g_Qh);
    cudaGetSymbolAddress(&pKh, g_Kh);
    cudaGetSymbolAddress(&pVt, g_Vt);
    cudaGetSymbolAddress(&pCtxH, g_ctx_h);

    cudaFuncSetAttribute(attn_mma,
                         cudaFuncAttributeMaxDynamicSharedMemorySize,
                         SMEM_ATTN);

    const int nBig4 = MROWS * DMODEL / 4;
    const int nW4 = DMODEL * DMODEL / 4;
    cvt_f32_f16<<<512, 256>>>(queries, (__half*)phA, nBig4);
    cvt_f32_f16<<<512, 256>>>(keys,    (__half*)phB, nBig4);
    cvt_f32_f16<<<256, 256>>>(Wq, (__half*)phWq, nW4);
    cvt_f32_f16<<<256, 256>>>(Wk, (__half*)phWk, nW4);
    cvt_f32_f16<<<256, 256>>>(Wv, (__half*)phWv, nW4);
    cvt_f32_f16<<<256, 256>>>(Wo, (__half*)phWo, nW4);

    const dim3 gg(MROWS / 128, DMODEL / 128);
    gemm_h<2><<<gg, 256>>>((const __half*)phA, (const __half*)phWq, pQh);
    gemm_h<1><<<gg, 256>>>((const __half*)phB, (const __half*)phWk, pKh);
    gemm_h<3><<<gg, 256>>>((const __half*)phB, (const __half*)phWv, pVt);

    attn_mma<<<dim3(LEN / 128, BATCH, NH), 256, SMEM_ATTN>>>(seqlen);

    gemm_h<0><<<gg, 256>>>((const __half*)pCtxH, (const __half*)phWo, out);
}

// round 10
// speedup vs baseline: 3.1501x; 1.0922x over previous
#include <cuda_runtime.h>
#include <cuda_fp16.h>
#include <cstdint>
#include <math.h>

#define BATCH 4
#define LEN 2048
#define DMODEL 1024
#define NH 8
#define DHEAD 128
#define MROWS (BATCH * LEN)

// fp16 GEMM operands
__device__ __half g_hA[MROWS * DMODEL];
__device__ __half g_hB[MROWS * DMODEL];
__device__ __half g_hWq[DMODEL * DMODEL];
__device__ __half g_hWk[DMODEL * DMODEL];
__device__ __half g_hWv[DMODEL * DMODEL];
__device__ __half g_hWo[DMODEL * DMODEL];
// fp16 attention operands
__device__ __half g_Qh[NH * BATCH * LEN * DHEAD];   // [h][b][l][d], pre-scaled
__device__ __half g_Kh[NH * BATCH * LEN * DHEAD];   // [h][b][l][d]
__device__ __half g_Vt[NH * BATCH * DHEAD * LEN];   // [h][b][d][l] transposed
__device__ __half g_ctx_h[BATCH * LEN * DMODEL];    // [b][l][h*128+d]

#define QSCL 0.08838834764831845f

// ---------------------------------------------------------------------------
__device__ __forceinline__ void mma_f16(float& d0, float& d1, float& d2,
                                        float& d3, uint32_t a0, uint32_t a1,
                                        uint32_t a2, uint32_t a3, uint32_t b0,
                                        uint32_t b1) {
    asm volatile(
        "mma.sync.aligned.m16n8k16.row.col.f32.f16.f16.f32 "
        "{%0,%1,%2,%3}, {%4,%5,%6,%7}, {%8,%9}, {%0,%1,%2,%3};"
        : "+f"(d0), "+f"(d1), "+f"(d2), "+f"(d3)
        : "r"(a0), "r"(a1), "r"(a2), "r"(a3), "r"(b0), "r"(b1));
}

__device__ __forceinline__ void ldsm_x4(uint32_t& r0, uint32_t& r1,
                                        uint32_t& r2, uint32_t& r3,
                                        uint32_t addr) {
    asm volatile(
        "ldmatrix.sync.aligned.m8n8.x4.shared.b16 {%0,%1,%2,%3}, [%4];"
        : "=r"(r0), "=r"(r1), "=r"(r2), "=r"(r3) : "r"(addr));
}

__device__ __forceinline__ uint32_t smem_u32(const void* p) {
    uint32_t a;
    asm("{ .reg .u64 t; cvta.to.shared.u64 t, %1; cvt.u32.u64 %0, t; }"
        : "=r"(a) : "l"(p));
    return a;
}

__device__ __forceinline__ uint32_t pack_h2(float a, float b) {
    const __half2 h = __floats2half2_rn(a, b);
    return *(const uint32_t*)&h;
}

#define CP_ASYNC16(dst_u32, src_ptr)                                          \
    asm volatile("cp.async.cg.shared.global [%0], [%1], 16;"                  \
                 :: "r"(dst_u32), "l"(src_ptr) : "memory")
#define CP_COMMIT() asm volatile("cp.async.commit_group;" ::: "memory")
#define CP_WAIT(n)  asm volatile("cp.async.wait_group %0;" :: "n"(n) : "memory")

// ===========================================================================
__global__ void __launch_bounds__(256)
cvt_f32_f16(const float* __restrict__ src, __half* __restrict__ dst, int n4)
{
    const int stride = gridDim.x * blockDim.x;
    for (int i = blockIdx.x * blockDim.x + threadIdx.x; i < n4; i += stride) {
        const float4 v = *(const float4*)(src + i * 4);
        __half2* d = (__half2*)(dst + i * 4);
        d[0] = __floats2half2_rn(v.x, v.y);
        d[1] = __floats2half2_rn(v.z, v.w);
    }
}

// ===========================================================================
// fp16 mma.sync NT-GEMM with ldmatrix fragment loads.
// MODEs: 0 fp32 out; 1 fp16 scatter; 2 fp16 scatter*QSCL; 3 fp16 transposed.
// ===========================================================================
#define HSP 20
#define HSTG (128 * HSP)
#define HNIT (DMODEL / 32)

template <int MODE>
__global__ void __launch_bounds__(256)
gemm_h(const __half* __restrict__ A, const __half* __restrict__ W, void* Cv)
{
    __shared__ uint32_t sh[2 * 2 * HSTG];
    const uint32_t sb = smem_u32(sh);

    const int tid = threadIdx.x;
    const int wid = tid >> 5;
    const int lane = tid & 31;
    const int wm = (wid >> 2) * 64;
    const int wn = (wid & 3) * 32;
    const int r = lane >> 2;
    const int c = lane & 3;
    const int m0 = blockIdx.x * 128;
    const int n0 = blockIdx.y * 128;

    // ldmatrix lane-derived indices
    const int lx = lane & 15;            // A-style row-in-16
    const int lhiA = (lane >> 4) * 4;    // A-style col half (u32)
    const int l8 = lane & 7;             // B-style row-in-8
    const int lgB = (lane >> 4) * 8;     // B-style row group
    const int lqB = ((lane >> 3) & 1) * 4;   // B-style col half (u32)

    const int lrow = tid >> 1;
    const int lch = (tid & 1) * 2;

    const __half* Ag = A + (size_t)(m0 + lrow) * DMODEL + lch * 8;
    const __half* Wg = W + (size_t)(n0 + lrow) * DMODEL + lch * 8;
    const uint32_t dstA = sb + (lrow * HSP + lch * 4) * 4;
    const uint32_t dstW = sb + (HSTG + lrow * HSP + lch * 4) * 4;

    float acc[4][4][4];
#pragma unroll
    for (int i = 0; i < 4; i++)
#pragma unroll
        for (int j = 0; j < 4; j++)
#pragma unroll
            for (int q = 0; q < 4; q++) acc[i][j][q] = 0.0f;

#pragma unroll
    for (int pre = 0; pre < 2; pre++) {
        const int k0 = pre * 32;
        const uint32_t so = pre * 2 * HSTG * 4;
        CP_ASYNC16(dstA + so, Ag + k0);
        CP_ASYNC16(dstA + so + 16, Ag + k0 + 8);
        CP_ASYNC16(dstW + so, Wg + k0);
        CP_ASYNC16(dstW + so + 16, Wg + k0 + 8);
        CP_COMMIT();
    }

    for (int it = 0; it < HNIT; it++) {
        const int stg = it & 1;
        const uint32_t sA = sb + (stg * 2 * HSTG) * 4;
        const uint32_t sW = sA + HSTG * 4;

        CP_WAIT(1);
        __syncthreads();

#pragma unroll
        for (int ks = 0; ks < 2; ks++) {
            uint32_t af[4][4];
#pragma unroll
            for (int mt = 0; mt < 4; mt++) {
                const uint32_t a =
                    sA + ((wm + mt * 16 + lx) * HSP + ks * 8 + lhiA) * 4;
                ldsm_x4(af[mt][0], af[mt][1], af[mt][2], af[mt][3], a);
            }
            uint32_t bf[4][2];
#pragma unroll
            for (int p = 0; p < 2; p++) {
                const uint32_t a =
                    sW + ((wn + p * 16 + lgB + l8) * HSP + ks * 8 + lqB) * 4;
                ldsm_x4(bf[2 * p][0], bf[2 * p][1], bf[2 * p + 1][0],
                        bf[2 * p + 1][1], a);
            }
#pragma unroll
            for (int mt = 0; mt < 4; mt++)
#pragma unroll
                for (int nt = 0; nt < 4; nt++)
                    mma_f16(acc[mt][nt][0], acc[mt][nt][1], acc[mt][nt][2],
                            acc[mt][nt][3], af[mt][0], af[mt][1], af[mt][2],
                            af[mt][3], bf[nt][0], bf[nt][1]);
        }

        __syncthreads();
        const int nxt = it + 2;
        if (nxt < HNIT) {
            const int k0 = nxt * 32;
            const uint32_t so = stg * 2 * HSTG * 4;
            CP_ASYNC16(dstA + so, Ag + k0);
            CP_ASYNC16(dstA + so + 16, Ag + k0 + 8);
            CP_ASYNC16(dstW + so, Wg + k0);
            CP_ASYNC16(dstW + so + 16, Wg + k0 + 8);
        }
        CP_COMMIT();
    }

    // epilogue
#pragma unroll
    for (int mt = 0; mt < 4; mt++) {
#pragma unroll
        for (int half = 0; half < 2; half++) {
            const int mrow = m0 + wm + mt * 16 + r + half * 8;
            const int bb = mrow >> 11;
            const int ll = mrow & (LEN - 1);
            const int hh = n0 >> 7;
#pragma unroll
            for (int nt = 0; nt < 4; nt++) {
                const int ncol = wn + nt * 8 + 2 * c;
                float v0 = acc[mt][nt][half * 2];
                float v1 = acc[mt][nt][half * 2 + 1];
                if (MODE == 0) {
                    float* dst = (float*)Cv + (size_t)mrow * DMODEL + n0;
                    *(float2*)(dst + ncol) = make_float2(v0, v1);
                } else if (MODE == 1 || MODE == 2) {
                    if (MODE == 2) { v0 *= QSCL; v1 *= QSCL; }
                    __half* dst = (__half*)Cv +
                        (((size_t)(hh * BATCH + bb) * LEN + ll) << 7);
                    *(__half2*)(dst + ncol) = __floats2half2_rn(v0, v1);
                } else {
                    __half* base = (__half*)Cv +
                        (size_t)(hh * BATCH + bb) * DHEAD * LEN;
                    base[(size_t)ncol * LEN + ll] = __float2half_rn(v0);
                    base[(size_t)(ncol + 1) * LEN + ll] = __float2half_rn(v1);
                }
            }
        }
    }
}

// ===========================================================================
// Flash attention, fp16 mma + ldmatrix fragment loads + cp.async pipeline.
// ===========================================================================
#define KP2 68
#define VP2 36
#define STGH (64 * KP2 + 128 * VP2)
#define SMA_PS2 (2 * STGH)
#define SMA_TOT2 (SMA_PS2 + 128 * VP2)
#define SMEM_ATTN (SMA_TOT2 * (int)sizeof(uint32_t))

__global__ void __launch_bounds__(256)
attn_mma(const int* __restrict__ seq)
{
    extern __shared__ uint32_t sm[];
    const uint32_t sb = smem_u32(sm);
    uint32_t* Ps = sm + SMA_PS2;
    const uint32_t sbPs = sb + SMA_PS2 * 4;

    const int tid = threadIdx.x;
    const int wid = tid >> 5;
    const int lane = tid & 31;
    const int r = lane >> 2;
    const int c = lane & 3;
    const int qt = blockIdx.x, b = blockIdx.y, h = blockIdx.z;
    const int qbase = qt * 128;
    const int slen = seq[b];
    const int q0 = wid * 16;

    // ldmatrix lane indices
    const int lx = lane & 15;
    const int lhiA = (lane >> 4) * 4;
    const int l8 = lane & 7;
    const int lgB = (lane >> 4) * 8;
    const int lqB = ((lane >> 3) & 1) * 4;

    __half* ctx = g_ctx_h + (size_t)b * LEN * DMODEL + (size_t)h * DHEAD;

    if (qbase >= slen) {
#pragma unroll
        for (int it = 0; it < 8; it++) {
            const int f = tid + it * 256;
            const int row = f >> 4;
            const int cu = (f & 15) * 8;
            *(uint4*)(ctx + (size_t)(qbase + row) * DMODEL + cu) =
                make_uint4(0, 0, 0, 0);
        }
        return;
    }

    const __half* Qg = g_Qh + (((size_t)h * BATCH + b) * LEN + qbase) * DHEAD;
    const __half* Kg = g_Kh + ((size_t)h * BATCH + b) * LEN * DHEAD;
    const __half* Vg = g_Vt + ((size_t)h * BATCH + b) * DHEAD * LEN;

    const int nkt = (slen + 63) >> 6;

    // ---- Q staging (aliases stage 0) ----
#pragma unroll
    for (int it = 0; it < 8; it++) {
        const int f = tid + it * 256;
        const int row = f >> 4;
        const int ch = f & 15;
        CP_ASYNC16(sb + (row * KP2 + ch * 4) * 4,
                   Qg + (size_t)row * DHEAD + ch * 8);
    }
    CP_COMMIT();
    CP_WAIT(0);
    __syncthreads();

    uint32_t qf[8][4];
#pragma unroll
    for (int ks = 0; ks < 8; ks++) {
        const uint32_t a = sb + ((q0 + lx) * KP2 + ks * 8 + lhiA) * 4;
        ldsm_x4(qf[ks][0], qf[ks][1], qf[ks][2], qf[ks][3], a);
    }
    __syncthreads();

    // prologue stages 0,1
#pragma unroll 1
    for (int pre = 0; pre < 2; pre++) {
        if (pre < nkt) {
            const int kb = pre * 64;
            const uint32_t kbase = sb + (pre * STGH) * 4;
            const uint32_t vbase = sb + (pre * STGH + 64 * KP2) * 4;
#pragma unroll
            for (int it = 0; it < 4; it++) {
                const int f = tid + it * 256;
                const int row = f >> 4;
                const int ch = f & 15;
                CP_ASYNC16(kbase + (row * KP2 + ch * 4) * 4,
                           Kg + (size_t)(kb + row) * DHEAD + ch * 8);
            }
#pragma unroll
            for (int it = 0; it < 4; it++) {
                const int f = tid + it * 256;
                const int d = f >> 3;
                const int ch = f & 7;
                CP_ASYNC16(vbase + (d * VP2 + ch * 4) * 4,
                           Vg + (size_t)d * LEN + kb + ch * 8);
            }
        }
        CP_COMMIT();
    }

    float o[16][4];
#pragma unroll
    for (int nt = 0; nt < 16; nt++)
#pragma unroll
        for (int q = 0; q < 4; q++) o[nt][q] = 0.0f;
    float m0v = -1e30f, m1v = -1e30f, l0 = 0.0f, l1 = 0.0f;

    for (int kt = 0; kt < nkt; kt++) {
        const int kb = kt * 64;
        const int stg = kt & 1;
        const uint32_t sK = sb + (stg * STGH) * 4;
        const uint32_t sV = sK + (64 * KP2) * 4;

        CP_WAIT(1);
        __syncthreads();

        // S = Q K^T
        float s[8][4];
#pragma unroll
        for (int nt = 0; nt < 8; nt++)
#pragma unroll
            for (int q = 0; q < 4; q++) s[nt][q] = 0.0f;

#pragma unroll
        for (int ks = 0; ks < 8; ks++) {
            uint32_t bf[8][2];
#pragma unroll
            for (int p = 0; p < 4; p++) {
                const uint32_t a =
                    sK + ((p * 16 + lgB + l8) * KP2 + ks * 8 + lqB) * 4;
                ldsm_x4(bf[2 * p][0], bf[2 * p][1], bf[2 * p + 1][0],
                        bf[2 * p + 1][1], a);
            }
#pragma unroll
            for (int nt = 0; nt < 8; nt++)
                mma_f16(s[nt][0], s[nt][1], s[nt][2], s[nt][3],
                        qf[ks][0], qf[ks][1], qf[ks][2], qf[ks][3],
                        bf[nt][0], bf[nt][1]);
        }

        // key mask
#pragma unroll
        for (int nt = 0; nt < 8; nt++) {
            const int j0 = kb + nt * 8 + 2 * c;
            if (j0 >= slen)     { s[nt][0] = -1e30f; s[nt][2] = -1e30f; }
            if (j0 + 1 >= slen) { s[nt][1] = -1e30f; s[nt][3] = -1e30f; }
        }

        // online softmax
        float mt0 = -1e30f, mt1 = -1e30f;
#pragma unroll
        for (int nt = 0; nt < 8; nt++) {
            mt0 = fmaxf(mt0, fmaxf(s[nt][0], s[nt][1]));
            mt1 = fmaxf(mt1, fmaxf(s[nt][2], s[nt][3]));
        }
        mt0 = fmaxf(mt0, __shfl_xor_sync(0xffffffffu, mt0, 1));
        mt0 = fmaxf(mt0, __shfl_xor_sync(0xffffffffu, mt0, 2));
        mt1 = fmaxf(mt1, __shfl_xor_sync(0xffffffffu, mt1, 1));
        mt1 = fmaxf(mt1, __shfl_xor_sync(0xffffffffu, mt1, 2));

        const float mn0 = fmaxf(m0v, mt0);
        const float mn1 = fmaxf(m1v, mt1);
        const float sc0 = __expf(m0v - mn0);
        const float sc1 = __expf(m1v - mn1);
        m0v = mn0; m1v = mn1;

        float rs0 = 0.0f, rs1 = 0.0f;
#pragma unroll
        for (int nt = 0; nt < 8; nt++) {
            const float p0 = __expf(s[nt][0] - mn0);
            const float p1 = __expf(s[nt][1] - mn0);
            const float p2 = __expf(s[nt][2] - mn1);
            const float p3 = __expf(s[nt][3] - mn1);
            rs0 += p0 + p1;
            rs1 += p2 + p3;
            Ps[(q0 + r) * VP2 + nt * 4 + c] = pack_h2(p0, p1);
            Ps[(q0 + r + 8) * VP2 + nt * 4 + c] = pack_h2(p2, p3);
        }
        rs0 += __shfl_xor_sync(0xffffffffu, rs0, 1);
        rs0 += __shfl_xor_sync(0xffffffffu, rs0, 2);
        rs1 += __shfl_xor_sync(0xffffffffu, rs1, 1);
        rs1 += __shfl_xor_sync(0xffffffffu, rs1, 2);
        l0 = l0 * sc0 + rs0;
        l1 = l1 * sc1 + rs1;

#pragma unroll
        for (int nt = 0; nt < 16; nt++) {
            o[nt][0] *= sc0; o[nt][1] *= sc0;
            o[nt][2] *= sc1; o[nt][3] *= sc1;
        }
        __syncwarp();

        // O += P @ V
#pragma unroll
        for (int ks = 0; ks < 4; ks++) {
            uint32_t af[4];
            {
                const uint32_t a =
                    sbPs + ((q0 + lx) * VP2 + ks * 8 + lhiA) * 4;
                ldsm_x4(af[0], af[1], af[2], af[3], a);
            }
#pragma unroll
            for (int p = 0; p < 8; p++) {
                uint32_t b0a, b0b, b1a, b1b;
                const uint32_t a =
                    sV + ((p * 16 + lgB + l8) * VP2 + ks * 8 + lqB) * 4;
                ldsm_x4(b0a, b0b, b1a, b1b, a);
                mma_f16(o[2 * p][0], o[2 * p][1], o[2 * p][2], o[2 * p][3],
                        af[0], af[1], af[2], af[3], b0a, b0b);
                mma_f16(o[2 * p + 1][0], o[2 * p + 1][1], o[2 * p + 1][2],
                        o[2 * p + 1][3], af[0], af[1], af[2], af[3], b1a, b1b);
            }
        }

        __syncthreads();

        const int nxt = kt + 2;
        if (nxt < nkt) {
            const int kb2 = nxt * 64;
            const uint32_t kbase = sb + (stg * STGH) * 4;
            const uint32_t vbase = sb + (stg * STGH + 64 * KP2) * 4;
#pragma unroll
            for (int it = 0; it < 4; it++) {
                const int f = tid + it * 256;
                const int row = f >> 4;
                const int ch = f & 15;
                CP_ASYNC16(kbase + (row * KP2 + ch * 4) * 4,
                           Kg + (size_t)(kb2 + row) * DHEAD + ch * 8);
            }
#pragma unroll
            for (int it = 0; it < 4; it++) {
                const int f = tid + it * 256;
                const int d = f >> 3;
                const int ch = f & 7;
                CP_ASYNC16(vbase + (d * VP2 + ch * 4) * 4,
                           Vg + (size_t)d * LEN + kb2 + ch * 8);
            }
        }
        CP_COMMIT();
    }

    // epilogue
    const int qr0 = qbase + q0 + r;
    const int qr1 = qr0 + 8;
    const float inv0 = (qr0 < slen) ? (1.0f / l0) : 0.0f;
    const float inv1 = (qr1 < slen) ? (1.0f / l1) : 0.0f;
#pragma unroll
    for (int nt = 0; nt < 16; nt++) {
        const int col = nt * 8 + 2 * c;
        *(__half2*)(ctx + (size_t)qr0 * DMODEL + col) =
            __floats2half2_rn(o[nt][0] * inv0, o[nt][1] * inv0);
        *(__half2*)(ctx + (size_t)qr1 * DMODEL + col) =
            __floats2half2_rn(o[nt][2] * inv1, o[nt][3] * inv1);
    }
}

// ===========================================================================
extern "C" void kernel_launch(void* const* d_in, const int* in_sizes, int n_in,
                              void* d_out, int out_size)
{
    (void)in_sizes; (void)n_in; (void)out_size;
    const float* queries = (const float*)d_in[0];
    const float* keys    = (const float*)d_in[1];
    const int*   seqlen  = (const int*)d_in[2];
    const float* Wq      = (const float*)d_in[3];
    const float* Wk      = (const float*)d_in[4];
    const float* Wv      = (const float*)d_in[5];
    const float* Wo      = (const float*)d_in[6];
    float* out = (float*)d_out;

    void *phA, *phB, *phWq, *phWk, *phWv, *phWo, *pQh, *pKh, *pVt, *pCtxH;
    cudaGetSymbolAddress(&phA, g_hA);
    cudaGetSymbolAddress(&phB, g_hB);
    cudaGetSymbolAddress(&phWq, g_hWq);
    cudaGetSymbolAddress(&phWk, g_hWk);
    cudaGetSymbolAddress(&phWv, g_hWv);
    cudaGetSymbolAddress(&phWo, g_hWo);
    cudaGetSymbolAddress(&pQh, g_Qh);
    cudaGetSymbolAddress(&pKh, g_Kh);
    cudaGetSymbolAddress(&pVt, g_Vt);
    cudaGetSymbolAddress(&pCtxH, g_ctx_h);

    cudaFuncSetAttribute(attn_mma,
                         cudaFuncAttributeMaxDynamicSharedMemorySize,
                         SMEM_ATTN);

    const int nBig4 = MROWS * DMODEL / 4;
    const int nW4 = DMODEL * DMODEL / 4;
    cvt_f32_f16<<<512, 256>>>(queries, (__half*)phA, nBig4);
    cvt_f32_f16<<<512, 256>>>(keys,    (__half*)phB, nBig4);
    cvt_f32_f16<<<256, 256>>>(Wq, (__half*)phWq, nW4);
    cvt_f32_f16<<<256, 256>>>(Wk, (__half*)phWk, nW4);
    cvt_f32_f16<<<256, 256>>>(Wv, (__half*)phWv, nW4);
    cvt_f32_f16<<<256, 256>>>(Wo, (__half*)phWo, nW4);

    const dim3 gg(MROWS / 128, DMODEL / 128);
    gemm_h<2><<<gg, 256>>>((const __half*)phA, (const __half*)phWq, pQh);
    gemm_h<1><<<gg, 256>>>((const __half*)phB, (const __half*)phWk, pKh);
    gemm_h<3><<<gg, 256>>>((const __half*)phB, (const __half*)phWv, pVt);

    attn_mma<<<dim3(LEN / 128, BATCH, NH), 256, SMEM_ATTN>>>(seqlen);

    gemm_h<0><<<gg, 256>>>((const __half*)pCtxH, (const __half*)phWo, out);
}